// round 1
// baseline (speedup 1.0000x reference)
#include <cuda_runtime.h>
#include <math.h>

#define BD   2
#define SEQ  2048
#define DM   1024
#define NH   16
#define DH   64
#define MTOT (BD*SEQ)    // 4096
#define BHT  (BD*NH)     // 32

// scratch (allocation-free rule: __device__ globals)
__device__ float g_q [BHT*SEQ*DH];
__device__ float g_k [BHT*SEQ*DH];
__device__ float g_v [BHT*SEQ*DH];
__device__ float g_oh[BHT*SEQ*DH];

// ---------------------------------------------------------------------------
// QKV projection (+bias) with fused RoPE epilogue for q,k.
// C = x(4096x1024) @ W(1024x1024); tile 128x128x16, 8x8 per thread.
// blockIdx.z selects q/k/v.
// ---------------------------------------------------------------------------
__global__ __launch_bounds__(256) void qkv_kernel(
    const float* __restrict__ x,
    const float* __restrict__ wq, const float* __restrict__ bq,
    const float* __restrict__ wk, const float* __restrict__ bk,
    const float* __restrict__ wv, const float* __restrict__ bv)
{
    const int z = blockIdx.z;
    const float* W    = (z==0) ? wq : (z==1) ? wk : wv;
    const float* bias = (z==0) ? bq : (z==1) ? bk : bv;
    float* out        = (z==0) ? g_q : (z==1) ? g_k : g_v;

    __shared__ float As[16][128];
    __shared__ float Bs[16][128];
    __shared__ float s_freq[32];

    const int tid = threadIdx.x;
    const int m0 = blockIdx.y * 128;
    const int n0 = blockIdx.x * 128;

    if (tid < 32)
        s_freq[tid] = (float)(1.0 / pow(10000.0, (double)(2*tid) / 64.0));
    __syncthreads();

    const int la_m = tid & 127;
    const int la_k = (tid >> 7) * 4;        // 0 or 4
    const int lb_k = tid >> 5;              // 0..7
    const int lb_n = (tid & 31) * 4;
    const int ty = tid >> 4, tx = tid & 15;

    float acc[8][8];
    #pragma unroll
    for (int i = 0; i < 8; i++)
        #pragma unroll
        for (int j = 0; j < 8; j++) acc[i][j] = 0.f;

    for (int k0 = 0; k0 < DM; k0 += 16) {
        float4 a0 = *(const float4*)(x + (size_t)(m0+la_m)*DM + k0 + la_k);
        float4 a1 = *(const float4*)(x + (size_t)(m0+la_m)*DM + k0 + la_k + 8);
        As[la_k+0][la_m]=a0.x; As[la_k+1][la_m]=a0.y; As[la_k+2][la_m]=a0.z; As[la_k+3][la_m]=a0.w;
        As[la_k+8][la_m]=a1.x; As[la_k+9][la_m]=a1.y; As[la_k+10][la_m]=a1.z; As[la_k+11][la_m]=a1.w;
        *(float4*)&Bs[lb_k  ][lb_n] = *(const float4*)(W + (size_t)(k0+lb_k  )*DM + n0 + lb_n);
        *(float4*)&Bs[lb_k+8][lb_n] = *(const float4*)(W + (size_t)(k0+lb_k+8)*DM + n0 + lb_n);
        __syncthreads();
        #pragma unroll
        for (int kk = 0; kk < 16; kk++) {
            float4 av0 = *(float4*)&As[kk][ty*4];
            float4 av1 = *(float4*)&As[kk][64+ty*4];
            float4 bv0 = *(float4*)&Bs[kk][tx*4];
            float4 bv1 = *(float4*)&Bs[kk][64+tx*4];
            float a[8] = {av0.x,av0.y,av0.z,av0.w,av1.x,av1.y,av1.z,av1.w};
            float b[8] = {bv0.x,bv0.y,bv0.z,bv0.w,bv1.x,bv1.y,bv1.z,bv1.w};
            #pragma unroll
            for (int i = 0; i < 8; i++)
                #pragma unroll
                for (int j = 0; j < 8; j++)
                    acc[i][j] = fmaf(a[i], b[j], acc[i][j]);
        }
        __syncthreads();
    }

    #pragma unroll
    for (int i = 0; i < 8; i++) {
        int r = m0 + ty*4 + ((i < 4) ? i : (60 + i));   // rows ty*4+i and 64+ty*4+(i-4)
        int bb = r >> 11;
        int s  = r & 2047;
        #pragma unroll
        for (int jh = 0; jh < 2; jh++) {
            int cb = n0 + jh*64 + tx*4;
            float v0 = acc[i][jh*4+0] + bias[cb+0];
            float v1 = acc[i][jh*4+1] + bias[cb+1];
            float v2 = acc[i][jh*4+2] + bias[cb+2];
            float v3 = acc[i][jh*4+3] + bias[cb+3];
            int h  = cb >> 6;
            int d0 = cb & 63;
            float* dst = out + ((size_t)(bb*NH + h)*SEQ + s)*DH + d0;
            if (z < 2) {
                float f0 = s_freq[d0 >> 1];
                float f1 = s_freq[(d0 >> 1) + 1];
                float sn0, cs0, sn1, cs1;
                sincosf((float)s * f0, &sn0, &cs0);
                sincosf((float)s * f1, &sn1, &cs1);
                float4 o;
                o.x = v0*cs0 - v1*sn0;
                o.y = v0*sn0 + v1*cs0;
                o.z = v2*cs1 - v3*sn1;
                o.w = v2*sn1 + v3*cs1;
                *(float4*)dst = o;
            } else {
                *(float4*)dst = make_float4(v0, v1, v2, v3);
            }
        }
    }
}

// ---------------------------------------------------------------------------
// scores = (Q @ K^T) / 8 per (b,h). GEMM M=2048,N=2048,K=64, tile 128x128x16.
// Writes raw scaled scores to the attn region of d_out.
// ---------------------------------------------------------------------------
__global__ __launch_bounds__(256) void scores_kernel(float* __restrict__ attn)
{
    const int bh = blockIdx.z;
    const int m0 = blockIdx.y * 128;
    const int n0 = blockIdx.x * 128;
    const float* Q = g_q + (size_t)bh*SEQ*DH;
    const float* K = g_k + (size_t)bh*SEQ*DH;

    __shared__ float As[16][128];
    __shared__ float Bs[16][128];

    const int tid = threadIdx.x;
    const int lm = tid & 127;
    const int lk = (tid >> 7) * 4;
    const int ty = tid >> 4, tx = tid & 15;

    float acc[8][8];
    #pragma unroll
    for (int i = 0; i < 8; i++)
        #pragma unroll
        for (int j = 0; j < 8; j++) acc[i][j] = 0.f;

    for (int k0 = 0; k0 < DH; k0 += 16) {
        float4 a0 = *(const float4*)(Q + (size_t)(m0+lm)*DH + k0 + lk);
        float4 a1 = *(const float4*)(Q + (size_t)(m0+lm)*DH + k0 + lk + 8);
        float4 b0 = *(const float4*)(K + (size_t)(n0+lm)*DH + k0 + lk);
        float4 b1 = *(const float4*)(K + (size_t)(n0+lm)*DH + k0 + lk + 8);
        As[lk+0][lm]=a0.x; As[lk+1][lm]=a0.y; As[lk+2][lm]=a0.z; As[lk+3][lm]=a0.w;
        As[lk+8][lm]=a1.x; As[lk+9][lm]=a1.y; As[lk+10][lm]=a1.z; As[lk+11][lm]=a1.w;
        Bs[lk+0][lm]=b0.x; Bs[lk+1][lm]=b0.y; Bs[lk+2][lm]=b0.z; Bs[lk+3][lm]=b0.w;
        Bs[lk+8][lm]=b1.x; Bs[lk+9][lm]=b1.y; Bs[lk+10][lm]=b1.z; Bs[lk+11][lm]=b1.w;
        __syncthreads();
        #pragma unroll
        for (int kk = 0; kk < 16; kk++) {
            float4 av0 = *(float4*)&As[kk][ty*4];
            float4 av1 = *(float4*)&As[kk][64+ty*4];
            float4 bv0 = *(float4*)&Bs[kk][tx*4];
            float4 bv1 = *(float4*)&Bs[kk][64+tx*4];
            float a[8] = {av0.x,av0.y,av0.z,av0.w,av1.x,av1.y,av1.z,av1.w};
            float b[8] = {bv0.x,bv0.y,bv0.z,bv0.w,bv1.x,bv1.y,bv1.z,bv1.w};
            #pragma unroll
            for (int i = 0; i < 8; i++)
                #pragma unroll
                for (int j = 0; j < 8; j++)
                    acc[i][j] = fmaf(a[i], b[j], acc[i][j]);
        }
        __syncthreads();
    }

    float* base = attn + (size_t)bh*SEQ*SEQ;
    #pragma unroll
    for (int i = 0; i < 8; i++) {
        int r = m0 + ty*4 + ((i < 4) ? i : (60 + i));
        #pragma unroll
        for (int jh = 0; jh < 2; jh++) {
            int cb = n0 + jh*64 + tx*4;
            float4 o;
            o.x = acc[i][jh*4+0] * 0.125f;
            o.y = acc[i][jh*4+1] * 0.125f;
            o.z = acc[i][jh*4+2] * 0.125f;
            o.w = acc[i][jh*4+3] * 0.125f;
            *(float4*)(base + (size_t)r*SEQ + cb) = o;
        }
    }
}

// ---------------------------------------------------------------------------
// Row softmax over attn: 65536 rows x 2048, one block per row.
// ---------------------------------------------------------------------------
__global__ __launch_bounds__(256) void softmax_kernel(float* __restrict__ attn)
{
    float* p = attn + (size_t)blockIdx.x * SEQ;
    const int tid = threadIdx.x;

    float4 v0 = ((float4*)p)[tid];
    float4 v1 = ((float4*)p)[256 + tid];

    float mx = fmaxf(fmaxf(fmaxf(v0.x, v0.y), fmaxf(v0.z, v0.w)),
                     fmaxf(fmaxf(v1.x, v1.y), fmaxf(v1.z, v1.w)));
    __shared__ float red[8];
    #pragma unroll
    for (int o = 16; o; o >>= 1) mx = fmaxf(mx, __shfl_xor_sync(0xffffffffu, mx, o));
    if ((tid & 31) == 0) red[tid >> 5] = mx;
    __syncthreads();
    float bmax = red[0];
    #pragma unroll
    for (int w = 1; w < 8; w++) bmax = fmaxf(bmax, red[w]);
    __syncthreads();

    v0.x = __expf(v0.x - bmax); v0.y = __expf(v0.y - bmax);
    v0.z = __expf(v0.z - bmax); v0.w = __expf(v0.w - bmax);
    v1.x = __expf(v1.x - bmax); v1.y = __expf(v1.y - bmax);
    v1.z = __expf(v1.z - bmax); v1.w = __expf(v1.w - bmax);

    float sm = v0.x + v0.y + v0.z + v0.w + v1.x + v1.y + v1.z + v1.w;
    #pragma unroll
    for (int o = 16; o; o >>= 1) sm += __shfl_xor_sync(0xffffffffu, sm, o);
    if ((tid & 31) == 0) red[tid >> 5] = sm;
    __syncthreads();
    float bsum = 0.f;
    #pragma unroll
    for (int w = 0; w < 8; w++) bsum += red[w];
    float inv = 1.0f / bsum;

    v0.x *= inv; v0.y *= inv; v0.z *= inv; v0.w *= inv;
    v1.x *= inv; v1.y *= inv; v1.z *= inv; v1.w *= inv;
    ((float4*)p)[tid]       = v0;
    ((float4*)p)[256 + tid] = v1;
}

// ---------------------------------------------------------------------------
// PV: out_h = attn(2048x2048) @ V(2048x64) per (b,h). Tile 128x64x16.
// Thread computes 8 rows x 4 cols.
// ---------------------------------------------------------------------------
__global__ __launch_bounds__(256) void pv_kernel(const float* __restrict__ attn)
{
    const int bh = blockIdx.y;
    const int m0 = blockIdx.x * 128;
    const float* A = attn + (size_t)bh*SEQ*SEQ;
    const float* V = g_v  + (size_t)bh*SEQ*DH;

    __shared__ float As[16][128];
    __shared__ float Bs[16][64];

    const int tid = threadIdx.x;
    const int lm = tid & 127;
    const int lk = (tid >> 7) * 4;
    const int lb_k = tid >> 4;            // 0..15
    const int lb_n = (tid & 15) * 4;
    const int ty = tid >> 4, tx = tid & 15;

    float acc[8][4];
    #pragma unroll
    for (int i = 0; i < 8; i++)
        #pragma unroll
        for (int j = 0; j < 4; j++) acc[i][j] = 0.f;

    for (int k0 = 0; k0 < SEQ; k0 += 16) {
        float4 a0 = *(const float4*)(A + (size_t)(m0+lm)*SEQ + k0 + lk);
        float4 a1 = *(const float4*)(A + (size_t)(m0+lm)*SEQ + k0 + lk + 8);
        As[lk+0][lm]=a0.x; As[lk+1][lm]=a0.y; As[lk+2][lm]=a0.z; As[lk+3][lm]=a0.w;
        As[lk+8][lm]=a1.x; As[lk+9][lm]=a1.y; As[lk+10][lm]=a1.z; As[lk+11][lm]=a1.w;
        *(float4*)&Bs[lb_k][lb_n] = *(const float4*)(V + (size_t)(k0+lb_k)*DH + lb_n);
        __syncthreads();
        #pragma unroll
        for (int kk = 0; kk < 16; kk++) {
            float4 av0 = *(float4*)&As[kk][ty*4];
            float4 av1 = *(float4*)&As[kk][64+ty*4];
            float4 bv  = *(float4*)&Bs[kk][tx*4];
            float a[8] = {av0.x,av0.y,av0.z,av0.w,av1.x,av1.y,av1.z,av1.w};
            float b[4] = {bv.x,bv.y,bv.z,bv.w};
            #pragma unroll
            for (int i = 0; i < 8; i++)
                #pragma unroll
                for (int j = 0; j < 4; j++)
                    acc[i][j] = fmaf(a[i], b[j], acc[i][j]);
        }
        __syncthreads();
    }

    #pragma unroll
    for (int i = 0; i < 8; i++) {
        int r = m0 + ty*4 + ((i < 4) ? i : (60 + i));
        *(float4*)(g_oh + ((size_t)bh*SEQ + r)*DH + tx*4) =
            make_float4(acc[i][0], acc[i][1], acc[i][2], acc[i][3]);
    }
}

// ---------------------------------------------------------------------------
// Output projection: out = gather(oh) @ Wo + bo. M=4096,N=1024,K=1024.
// A[m][k] gathered from g_oh head-major layout.
// ---------------------------------------------------------------------------
__global__ __launch_bounds__(256) void outproj_kernel(
    const float* __restrict__ wo, const float* __restrict__ bo,
    float* __restrict__ out)
{
    __shared__ float As[16][128];
    __shared__ float Bs[16][128];

    const int tid = threadIdx.x;
    const int m0 = blockIdx.y * 128;
    const int n0 = blockIdx.x * 128;

    const int la_m = tid & 127;
    const int la_k = (tid >> 7) * 4;
    const int lb_k = tid >> 5;
    const int lb_n = (tid & 31) * 4;
    const int ty = tid >> 4, tx = tid & 15;

    const int m  = m0 + la_m;
    const int bb = m >> 11;
    const int s  = m & 2047;

    float acc[8][8];
    #pragma unroll
    for (int i = 0; i < 8; i++)
        #pragma unroll
        for (int j = 0; j < 8; j++) acc[i][j] = 0.f;

    for (int k0 = 0; k0 < DM; k0 += 16) {
        int k_a = k0 + la_k;
        int k_b = k0 + la_k + 8;
        size_t ia = ((size_t)(bb*NH + (k_a >> 6))*SEQ + s)*DH + (k_a & 63);
        size_t ib = ((size_t)(bb*NH + (k_b >> 6))*SEQ + s)*DH + (k_b & 63);
        float4 a0 = *(const float4*)(g_oh + ia);
        float4 a1 = *(const float4*)(g_oh + ib);
        As[la_k+0][la_m]=a0.x; As[la_k+1][la_m]=a0.y; As[la_k+2][la_m]=a0.z; As[la_k+3][la_m]=a0.w;
        As[la_k+8][la_m]=a1.x; As[la_k+9][la_m]=a1.y; As[la_k+10][la_m]=a1.z; As[la_k+11][la_m]=a1.w;
        *(float4*)&Bs[lb_k  ][lb_n] = *(const float4*)(wo + (size_t)(k0+lb_k  )*DM + n0 + lb_n);
        *(float4*)&Bs[lb_k+8][lb_n] = *(const float4*)(wo + (size_t)(k0+lb_k+8)*DM + n0 + lb_n);
        __syncthreads();
        #pragma unroll
        for (int kk = 0; kk < 16; kk++) {
            float4 av0 = *(float4*)&As[kk][ty*4];
            float4 av1 = *(float4*)&As[kk][64+ty*4];
            float4 bv0 = *(float4*)&Bs[kk][tx*4];
            float4 bv1 = *(float4*)&Bs[kk][64+tx*4];
            float a[8] = {av0.x,av0.y,av0.z,av0.w,av1.x,av1.y,av1.z,av1.w};
            float b[8] = {bv0.x,bv0.y,bv0.z,bv0.w,bv1.x,bv1.y,bv1.z,bv1.w};
            #pragma unroll
            for (int i = 0; i < 8; i++)
                #pragma unroll
                for (int j = 0; j < 8; j++)
                    acc[i][j] = fmaf(a[i], b[j], acc[i][j]);
        }
        __syncthreads();
    }

    #pragma unroll
    for (int i = 0; i < 8; i++) {
        int r = m0 + ty*4 + ((i < 4) ? i : (60 + i));
        #pragma unroll
        for (int jh = 0; jh < 2; jh++) {
            int cb = n0 + jh*64 + tx*4;
            float4 o;
            o.x = acc[i][jh*4+0] + bo[cb+0];
            o.y = acc[i][jh*4+1] + bo[cb+1];
            o.z = acc[i][jh*4+2] + bo[cb+2];
            o.w = acc[i][jh*4+3] + bo[cb+3];
            *(float4*)(out + (size_t)r*DM + cb) = o;
        }
    }
}

// ---------------------------------------------------------------------------
extern "C" void kernel_launch(void* const* d_in, const int* in_sizes, int n_in,
                              void* d_out, int out_size)
{
    const float* x  = (const float*)d_in[0];
    const float* wq = (const float*)d_in[1];
    const float* bq = (const float*)d_in[2];
    const float* wk = (const float*)d_in[3];
    const float* bk = (const float*)d_in[4];
    const float* wv = (const float*)d_in[5];
    const float* bv = (const float*)d_in[6];
    const float* wo = (const float*)d_in[7];
    const float* bo = (const float*)d_in[8];

    float* out  = (float*)d_out;
    float* attn = out + (size_t)MTOT * DM;   // tuple order: (out, attn)

    dim3 g1(8, 32, 3);
    qkv_kernel<<<g1, 256>>>(x, wq, bq, wk, bk, wv, bv);

    dim3 g2(16, 16, 32);
    scores_kernel<<<g2, 256>>>(attn);

    softmax_kernel<<<BHT * SEQ, 256>>>(attn);

    dim3 g4(16, 32);
    pv_kernel<<<g4, 256>>>(attn);

    dim3 g5(8, 32);
    outproj_kernel<<<g5, 256>>>(wo, bo, out);
}

// round 3
// speedup vs baseline: 1.4080x; 1.4080x over previous
#include <cuda_runtime.h>
#include <cuda_bf16.h>
#include <math.h>
#include <stdint.h>

#define BD   2
#define SEQ  2048
#define DM   1024
#define NH   16
#define DH   64
#define MTOT (BD*SEQ)    // 4096
#define BHT  (BD*NH)     // 32

// ---------------------------------------------------------------------------
// scratch (__device__ globals; allocation-free rule)
// ---------------------------------------------------------------------------
__device__ __nv_bfloat16 g_qh [BHT*SEQ*DH];
__device__ __nv_bfloat16 g_ql [BHT*SEQ*DH];
__device__ __nv_bfloat16 g_kh [BHT*SEQ*DH];
__device__ __nv_bfloat16 g_kl [BHT*SEQ*DH];
__device__ __nv_bfloat16 g_vh [BHT*SEQ*DH];   // V [bh][s][d] hi
__device__ __nv_bfloat16 g_vl [BHT*SEQ*DH];   // V lo
__device__ float g_psum[BHT*SEQ*16];          // per-(row, n-block) exp partial sums
__device__ float g_oh  [BHT*SEQ*DH];          // attention head outputs (fp32)

// ---------------------------------------------------------------------------
// warp-MMA helpers (sm_80+ PTX: works on plain sm_103 target)
// ---------------------------------------------------------------------------
__device__ __forceinline__ uint32_t smem_u32(const void* p) {
    uint32_t a;
    asm("{ .reg .u64 t; cvta.to.shared.u64 t, %1; cvt.u32.u64 %0, t; }" : "=r"(a) : "l"(p));
    return a;
}
__device__ __forceinline__ void ldsm4(uint32_t r[4], uint32_t addr) {
    asm volatile("ldmatrix.sync.aligned.m8n8.x4.shared.b16 {%0,%1,%2,%3}, [%4];"
        : "=r"(r[0]), "=r"(r[1]), "=r"(r[2]), "=r"(r[3]) : "r"(addr));
}
__device__ __forceinline__ void ldsm4t(uint32_t r[4], uint32_t addr) {
    asm volatile("ldmatrix.sync.aligned.m8n8.x4.trans.shared.b16 {%0,%1,%2,%3}, [%4];"
        : "=r"(r[0]), "=r"(r[1]), "=r"(r[2]), "=r"(r[3]) : "r"(addr));
}
__device__ __forceinline__ void mma16816(float* c, const uint32_t* a, uint32_t b0, uint32_t b1) {
    asm volatile("mma.sync.aligned.m16n8k16.row.col.f32.bf16.bf16.f32 "
        "{%0,%1,%2,%3}, {%4,%5,%6,%7}, {%8,%9}, {%0,%1,%2,%3};"
        : "+f"(c[0]), "+f"(c[1]), "+f"(c[2]), "+f"(c[3])
        : "r"(a[0]), "r"(a[1]), "r"(a[2]), "r"(a[3]), "r"(b0), "r"(b1));
}
// SW128-style swizzle for 128B-row tiles (conflict-free stores + ldmatrix)
#define SW(o) ((o) ^ (((o) >> 3) & 0x70))

__device__ __forceinline__ uint32_t pack_bf2(__nv_bfloat16 a, __nv_bfloat16 b) {
    return ((uint32_t)__bfloat16_as_ushort(b) << 16) | (uint32_t)__bfloat16_as_ushort(a);
}

// ---------------------------------------------------------------------------
// QKV projection (+bias), fp32 SIMT GEMM; epilogue:
//   q,k: RoPE then split to bf16 hi/lo ([bh][s][d])
//   v  : split to bf16 hi/lo ([bh][s][d])
// ---------------------------------------------------------------------------
__global__ __launch_bounds__(256) void qkv_kernel(
    const float* __restrict__ x,
    const float* __restrict__ wq, const float* __restrict__ bq,
    const float* __restrict__ wk, const float* __restrict__ bk,
    const float* __restrict__ wv, const float* __restrict__ bv)
{
    const int z = blockIdx.z;
    const float* W    = (z==0) ? wq : (z==1) ? wk : wv;
    const float* bias = (z==0) ? bq : (z==1) ? bk : bv;

    __shared__ float As[16][128];
    __shared__ float Bs[16][128];
    __shared__ float s_freq[32];

    const int tid = threadIdx.x;
    const int m0 = blockIdx.y * 128;
    const int n0 = blockIdx.x * 128;

    if (tid < 32)
        s_freq[tid] = (float)(1.0 / pow(10000.0, (double)(2*tid) / 64.0));
    __syncthreads();

    const int la_m = tid & 127;
    const int la_k = (tid >> 7) * 4;
    const int lb_k = tid >> 5;
    const int lb_n = (tid & 31) * 4;
    const int ty = tid >> 4, tx = tid & 15;

    float acc[8][8];
    #pragma unroll
    for (int i = 0; i < 8; i++)
        #pragma unroll
        for (int j = 0; j < 8; j++) acc[i][j] = 0.f;

    for (int k0 = 0; k0 < DM; k0 += 16) {
        float4 a0 = *(const float4*)(x + (size_t)(m0+la_m)*DM + k0 + la_k);
        float4 a1 = *(const float4*)(x + (size_t)(m0+la_m)*DM + k0 + la_k + 8);
        As[la_k+0][la_m]=a0.x; As[la_k+1][la_m]=a0.y; As[la_k+2][la_m]=a0.z; As[la_k+3][la_m]=a0.w;
        As[la_k+8][la_m]=a1.x; As[la_k+9][la_m]=a1.y; As[la_k+10][la_m]=a1.z; As[la_k+11][la_m]=a1.w;
        *(float4*)&Bs[lb_k  ][lb_n] = *(const float4*)(W + (size_t)(k0+lb_k  )*DM + n0 + lb_n);
        *(float4*)&Bs[lb_k+8][lb_n] = *(const float4*)(W + (size_t)(k0+lb_k+8)*DM + n0 + lb_n);
        __syncthreads();
        #pragma unroll
        for (int kk = 0; kk < 16; kk++) {
            float4 av0 = *(float4*)&As[kk][ty*4];
            float4 av1 = *(float4*)&As[kk][64+ty*4];
            float4 bv0 = *(float4*)&Bs[kk][tx*4];
            float4 bv1 = *(float4*)&Bs[kk][64+tx*4];
            float a[8] = {av0.x,av0.y,av0.z,av0.w,av1.x,av1.y,av1.z,av1.w};
            float b[8] = {bv0.x,bv0.y,bv0.z,bv0.w,bv1.x,bv1.y,bv1.z,bv1.w};
            #pragma unroll
            for (int i = 0; i < 8; i++)
                #pragma unroll
                for (int j = 0; j < 8; j++)
                    acc[i][j] = fmaf(a[i], b[j], acc[i][j]);
        }
        __syncthreads();
    }

    __nv_bfloat16* dh = (z==0) ? g_qh : (z==1) ? g_kh : g_vh;
    __nv_bfloat16* dl = (z==0) ? g_ql : (z==1) ? g_kl : g_vl;

    #pragma unroll
    for (int i = 0; i < 8; i++) {
        int r = m0 + ty*4 + ((i < 4) ? i : (60 + i));
        int bb = r >> 11;
        int s  = r & 2047;
        #pragma unroll
        for (int jh = 0; jh < 2; jh++) {
            int cb = n0 + jh*64 + tx*4;
            float v0 = acc[i][jh*4+0] + bias[cb+0];
            float v1 = acc[i][jh*4+1] + bias[cb+1];
            float v2 = acc[i][jh*4+2] + bias[cb+2];
            float v3 = acc[i][jh*4+3] + bias[cb+3];
            int h  = cb >> 6;
            int d0 = cb & 63;
            int bh = bb*NH + h;
            float ox = v0, oy = v1, oz = v2, ow = v3;
            if (z < 2) {
                float f0 = s_freq[d0 >> 1];
                float f1 = s_freq[(d0 >> 1) + 1];
                float sn0, cs0, sn1, cs1;
                sincosf((float)s * f0, &sn0, &cs0);
                sincosf((float)s * f1, &sn1, &cs1);
                ox = v0*cs0 - v1*sn0;
                oy = v0*sn0 + v1*cs0;
                oz = v2*cs1 - v3*sn1;
                ow = v2*sn1 + v3*cs1;
            }
            size_t idx = ((size_t)bh*SEQ + s)*DH + d0;
            __nv_bfloat16 hx=__float2bfloat16(ox), hy=__float2bfloat16(oy),
                          hz=__float2bfloat16(oz), hw=__float2bfloat16(ow);
            uint2 H; H.x = pack_bf2(hx,hy); H.y = pack_bf2(hz,hw);
            *(uint2*)(dh + idx) = H;
            __nv_bfloat16 lx=__float2bfloat16(ox-__bfloat162float(hx)),
                          ly=__float2bfloat16(oy-__bfloat162float(hy)),
                          lz=__float2bfloat16(oz-__bfloat162float(hz)),
                          lw=__float2bfloat16(ow-__bfloat162float(hw));
            uint2 L; L.x = pack_bf2(lx,ly); L.y = pack_bf2(lz,lw);
            *(uint2*)(dl + idx) = L;
        }
    }
}

// ---------------------------------------------------------------------------
// scores (HMMA bf16-split): block 128(M) x 128(N), K=64.
// 8 warps, warp = 64m x 32n. D = Qh@Kh^T + Qh@Kl^T + Ql@Kh^T.
// Epilogue: exp(D/8) unnormalized -> attn; partial rowsums -> g_psum.
// ---------------------------------------------------------------------------
#define SC_QH   0
#define SC_QL   16384
#define SC_KH   32768
#define SC_KL   49152
#define SC_SROW 65536
#define SC_SMEM (SC_SROW + 128*4*4)   // 67584

__global__ __launch_bounds__(256) void scores_mma_kernel(float* __restrict__ attn)
{
    extern __shared__ __align__(1024) char smem[];
    const uint32_t sb = smem_u32(smem);
    const int tid = threadIdx.x, wid = tid >> 5, lane = tid & 31;
    const int wy = wid >> 2, wx = wid & 3;     // warp tile: 64m x 32n
    const int nblk = blockIdx.x;
    const int n0 = nblk * 128;
    const int m0 = blockIdx.y * 128;
    const int bh = blockIdx.z;

    // load tiles: 128 rows x 64 bf16 (128B rows), SW swizzled
    {
        const uint4* qh = (const uint4*)(g_qh + ((size_t)bh*SEQ + m0)*DH);
        const uint4* ql = (const uint4*)(g_ql + ((size_t)bh*SEQ + m0)*DH);
        const uint4* kh = (const uint4*)(g_kh + ((size_t)bh*SEQ + n0)*DH);
        const uint4* kl = (const uint4*)(g_kl + ((size_t)bh*SEQ + n0)*DH);
        #pragma unroll
        for (int i = 0; i < 4; i++) {
            int c = tid + i*256;
            int row = c >> 3, part = c & 7;
            uint32_t off = SW((uint32_t)(row*128 + part*16));
            *(uint4*)(smem + SC_QH + off) = qh[row*8 + part];
            *(uint4*)(smem + SC_QL + off) = ql[row*8 + part];
            *(uint4*)(smem + SC_KH + off) = kh[row*8 + part];
            *(uint4*)(smem + SC_KL + off) = kl[row*8 + part];
        }
    }
    __syncthreads();

    float acc[4][4][4];
    #pragma unroll
    for (int a = 0; a < 4; a++)
        #pragma unroll
        for (int b = 0; b < 4; b++)
            #pragma unroll
            for (int c = 0; c < 4; c++) acc[a][b][c] = 0.f;

    const int arow = wy*64 + (lane & 7) + ((lane >> 3) & 1) * 8;
    #pragma unroll
    for (int ks = 0; ks < 4; ks++) {
        uint32_t ah[4][4], al[4][4];
        const uint32_t abase = (uint32_t)(arow*128 + ks*32 + (lane & 16));
        #pragma unroll
        for (int mt = 0; mt < 4; mt++) {
            uint32_t off = SW(abase + mt*16*128);
            ldsm4(ah[mt], sb + SC_QH + off);
            ldsm4(al[mt], sb + SC_QL + off);
        }
        #pragma unroll
        for (int np = 0; np < 2; np++) {
            const int g = lane >> 3;
            const int nrow = wx*32 + np*16 + (g >> 1)*8 + (lane & 7);
            const uint32_t boff = SW((uint32_t)(nrow*128 + ks*32 + (g & 1)*16));
            uint32_t bH[4], bL[4];
            ldsm4(bH, sb + SC_KH + boff);
            ldsm4(bL, sb + SC_KL + boff);
            #pragma unroll
            for (int mt = 0; mt < 4; mt++) {
                mma16816(acc[mt][np*2+0], ah[mt], bH[0], bH[1]);
                mma16816(acc[mt][np*2+0], ah[mt], bL[0], bL[1]);
                mma16816(acc[mt][np*2+0], al[mt], bH[0], bH[1]);
                mma16816(acc[mt][np*2+1], ah[mt], bH[2], bH[3]);
                mma16816(acc[mt][np*2+1], ah[mt], bL[2], bL[3]);
                mma16816(acc[mt][np*2+1], al[mt], bH[2], bH[3]);
            }
        }
    }

    // epilogue: exp + store + rowsums
    const int gr = lane >> 2, qc = (lane & 3) * 2;
    float* srw = (float*)(smem + SC_SROW);
    #pragma unroll
    for (int mt = 0; mt < 4; mt++) {
        #pragma unroll
        for (int h = 0; h < 2; h++) {
            int rl = wy*64 + mt*16 + h*8 + gr;
            float* arow_p = attn + ((size_t)bh*SEQ + m0 + rl)*SEQ + n0 + wx*32;
            float rs = 0.f;
            #pragma unroll
            for (int nt = 0; nt < 4; nt++) {
                float e0 = __expf(acc[mt][nt][h*2+0] * 0.125f);
                float e1 = __expf(acc[mt][nt][h*2+1] * 0.125f);
                rs += e0 + e1;
                *(float2*)(arow_p + nt*8 + qc) = make_float2(e0, e1);
            }
            rs += __shfl_xor_sync(0xffffffffu, rs, 1);
            rs += __shfl_xor_sync(0xffffffffu, rs, 2);
            if ((lane & 3) == 0) srw[rl*4 + wx] = rs;
        }
    }
    __syncthreads();
    if (tid < 128) {
        float s = srw[tid*4+0] + srw[tid*4+1] + srw[tid*4+2] + srw[tid*4+3];
        g_psum[((size_t)bh*SEQ + m0 + tid)*16 + nblk] = s;
    }
}

// ---------------------------------------------------------------------------
// pv (HMMA bf16-split): block 128(M) x 64(N), K=2048 in 32 tiles of 64.
// Normalizes P in-flight (writes normalized attn back), splits to bf16 hi/lo,
// V consumed via ldmatrix.trans from natural [s][d] layout.
// 8 warps, warp = 32m x 32n.
// ---------------------------------------------------------------------------
#define PV_INV  0
#define PV_PH   1024
#define PV_PL   (PV_PH + 16384)
#define PV_VH   (PV_PL + 16384)
#define PV_VL   (PV_VH + 8192)
#define PV_SMEM (PV_VL + 8192)   // 50176

__global__ __launch_bounds__(256) void pv_mma_kernel(float* __restrict__ attn)
{
    extern __shared__ __align__(1024) char smem[];
    const uint32_t sb = smem_u32(smem);
    const int tid = threadIdx.x, wid = tid >> 5, lane = tid & 31;
    const int wy = wid >> 1, wx = wid & 1;      // warp tile: 32m x 32n
    const int m0 = blockIdx.x * 128;
    const int bh = blockIdx.y;

    float* s_inv = (float*)(smem + PV_INV);
    if (tid < 128) {
        const float* ps = g_psum + ((size_t)bh*SEQ + m0 + tid)*16;
        float s = 0.f;
        #pragma unroll
        for (int j = 0; j < 16; j++) s += ps[j];
        s_inv[tid] = 1.f / s;
    }
    __syncthreads();

    float acc[2][4][4];
    #pragma unroll
    for (int a = 0; a < 2; a++)
        #pragma unroll
        for (int b = 0; b < 4; b++)
            #pragma unroll
            for (int c = 0; c < 4; c++) acc[a][b][c] = 0.f;

    const int prow0 = tid >> 4;
    const int col4  = (tid & 15) * 4;

    for (int kt = 0; kt < 32; kt++) {
        const int k0 = kt * 64;
        // P tile: read fp32, normalize, write back, split to bf16 hi/lo smem
        #pragma unroll
        for (int it = 0; it < 8; it++) {
            int row = prow0 + it*16;
            float* gp = attn + ((size_t)bh*SEQ + m0 + row)*SEQ + k0 + col4;
            float4 p = *(float4*)gp;
            float inv = s_inv[row];
            p.x *= inv; p.y *= inv; p.z *= inv; p.w *= inv;
            *(float4*)gp = p;
            __nv_bfloat16 hx=__float2bfloat16(p.x), hy=__float2bfloat16(p.y),
                          hz=__float2bfloat16(p.z), hw=__float2bfloat16(p.w);
            uint2 H; H.x = pack_bf2(hx,hy); H.y = pack_bf2(hz,hw);
            __nv_bfloat16 lx=__float2bfloat16(p.x-__bfloat162float(hx)),
                          ly=__float2bfloat16(p.y-__bfloat162float(hy)),
                          lz=__float2bfloat16(p.z-__bfloat162float(hz)),
                          lw=__float2bfloat16(p.w-__bfloat162float(hw));
            uint2 L; L.x = pack_bf2(lx,ly); L.y = pack_bf2(lz,lw);
            uint32_t off = SW((uint32_t)(row*128 + col4*2));
            *(uint2*)(smem + PV_PH + off) = H;
            *(uint2*)(smem + PV_PL + off) = L;
        }
        // V tile: 64 s-rows x 64 d (128B rows), hi/lo
        #pragma unroll
        for (int i = 0; i < 2; i++) {
            int c = tid + i*256;
            int srow = c >> 3, part = c & 7;
            uint32_t off = SW((uint32_t)(srow*128 + part*16));
            size_t gi = ((size_t)bh*SEQ + k0 + srow)*DH + part*8;
            *(uint4*)(smem + PV_VH + off) = *(const uint4*)(g_vh + gi);
            *(uint4*)(smem + PV_VL + off) = *(const uint4*)(g_vl + gi);
        }
        __syncthreads();

        const int arow = wy*32 + (lane & 7) + ((lane >> 3) & 1) * 8;
        #pragma unroll
        for (int ks = 0; ks < 4; ks++) {
            uint32_t ah[2][4], al[2][4];
            const uint32_t abase = (uint32_t)(arow*128 + ks*32 + (lane & 16));
            #pragma unroll
            for (int mt = 0; mt < 2; mt++) {
                uint32_t off = SW(abase + mt*16*128);
                ldsm4(ah[mt], sb + PV_PH + off);
                ldsm4(al[mt], sb + PV_PL + off);
            }
            #pragma unroll
            for (int np = 0; np < 2; np++) {
                const int g = lane >> 3;
                const int krow = ks*16 + (g & 1)*8 + (lane & 7);
                const int ncol = wx*32 + np*16 + (g >> 1)*8;
                const uint32_t boff = SW((uint32_t)(krow*128 + ncol*2));
                uint32_t bH[4], bL[4];
                ldsm4t(bH, sb + PV_VH + boff);
                ldsm4t(bL, sb + PV_VL + boff);
                #pragma unroll
                for (int mt = 0; mt < 2; mt++) {
                    mma16816(acc[mt][np*2+0], ah[mt], bH[0], bH[1]);
                    mma16816(acc[mt][np*2+0], ah[mt], bL[0], bL[1]);
                    mma16816(acc[mt][np*2+0], al[mt], bH[0], bH[1]);
                    mma16816(acc[mt][np*2+1], ah[mt], bH[2], bH[3]);
                    mma16816(acc[mt][np*2+1], ah[mt], bL[2], bL[3]);
                    mma16816(acc[mt][np*2+1], al[mt], bH[2], bH[3]);
                }
            }
        }
        __syncthreads();
    }

    // epilogue: write head outputs (fp32)
    const int gr = lane >> 2, qc = (lane & 3) * 2;
    #pragma unroll
    for (int mt = 0; mt < 2; mt++) {
        #pragma unroll
        for (int h = 0; h < 2; h++) {
            int rl = wy*32 + mt*16 + h*8 + gr;
            float* orow = g_oh + ((size_t)bh*SEQ + m0 + rl)*DH + wx*32;
            #pragma unroll
            for (int nt = 0; nt < 4; nt++)
                *(float2*)(orow + nt*8 + qc) =
                    make_float2(acc[mt][nt][h*2+0], acc[mt][nt][h*2+1]);
        }
    }
}

// ---------------------------------------------------------------------------
// Output projection: out = gather(g_oh) @ Wo + bo (fp32 SIMT)
// ---------------------------------------------------------------------------
__global__ __launch_bounds__(256) void outproj_kernel(
    const float* __restrict__ wo, const float* __restrict__ bo,
    float* __restrict__ out)
{
    __shared__ float As[16][128];
    __shared__ float Bs[16][128];

    const int tid = threadIdx.x;
    const int m0 = blockIdx.y * 128;
    const int n0 = blockIdx.x * 128;

    const int la_m = tid & 127;
    const int la_k = (tid >> 7) * 4;
    const int lb_k = tid >> 5;
    const int lb_n = (tid & 31) * 4;
    const int ty = tid >> 4, tx = tid & 15;

    const int m  = m0 + la_m;
    const int bb = m >> 11;
    const int s  = m & 2047;

    float acc[8][8];
    #pragma unroll
    for (int i = 0; i < 8; i++)
        #pragma unroll
        for (int j = 0; j < 8; j++) acc[i][j] = 0.f;

    for (int k0 = 0; k0 < DM; k0 += 16) {
        int k_a = k0 + la_k;
        int k_b = k0 + la_k + 8;
        size_t ia = ((size_t)(bb*NH + (k_a >> 6))*SEQ + s)*DH + (k_a & 63);
        size_t ib = ((size_t)(bb*NH + (k_b >> 6))*SEQ + s)*DH + (k_b & 63);
        float4 a0 = *(const float4*)(g_oh + ia);
        float4 a1 = *(const float4*)(g_oh + ib);
        As[la_k+0][la_m]=a0.x; As[la_k+1][la_m]=a0.y; As[la_k+2][la_m]=a0.z; As[la_k+3][la_m]=a0.w;
        As[la_k+8][la_m]=a1.x; As[la_k+9][la_m]=a1.y; As[la_k+10][la_m]=a1.z; As[la_k+11][la_m]=a1.w;
        *(float4*)&Bs[lb_k  ][lb_n] = *(const float4*)(wo + (size_t)(k0+lb_k  )*DM + n0 + lb_n);
        *(float4*)&Bs[lb_k+8][lb_n] = *(const float4*)(wo + (size_t)(k0+lb_k+8)*DM + n0 + lb_n);
        __syncthreads();
        #pragma unroll
        for (int kk = 0; kk < 16; kk++) {
            float4 av0 = *(float4*)&As[kk][ty*4];
            float4 av1 = *(float4*)&As[kk][64+ty*4];
            float4 bv0 = *(float4*)&Bs[kk][tx*4];
            float4 bv1 = *(float4*)&Bs[kk][64+tx*4];
            float a[8] = {av0.x,av0.y,av0.z,av0.w,av1.x,av1.y,av1.z,av1.w};
            float b[8] = {bv0.x,bv0.y,bv0.z,bv0.w,bv1.x,bv1.y,bv1.z,bv1.w};
            #pragma unroll
            for (int i = 0; i < 8; i++)
                #pragma unroll
                for (int j = 0; j < 8; j++)
                    acc[i][j] = fmaf(a[i], b[j], acc[i][j]);
        }
        __syncthreads();
    }

    #pragma unroll
    for (int i = 0; i < 8; i++) {
        int r = m0 + ty*4 + ((i < 4) ? i : (60 + i));
        #pragma unroll
        for (int jh = 0; jh < 2; jh++) {
            int cb = n0 + jh*64 + tx*4;
            float4 o;
            o.x = acc[i][jh*4+0] + bo[cb+0];
            o.y = acc[i][jh*4+1] + bo[cb+1];
            o.z = acc[i][jh*4+2] + bo[cb+2];
            o.w = acc[i][jh*4+3] + bo[cb+3];
            *(float4*)(out + (size_t)r*DM + cb) = o;
        }
    }
}

// ---------------------------------------------------------------------------
extern "C" void kernel_launch(void* const* d_in, const int* in_sizes, int n_in,
                              void* d_out, int out_size)
{
    const float* x  = (const float*)d_in[0];
    const float* wq = (const float*)d_in[1];
    const float* bq = (const float*)d_in[2];
    const float* wk = (const float*)d_in[3];
    const float* bk = (const float*)d_in[4];
    const float* wv = (const float*)d_in[5];
    const float* bv = (const float*)d_in[6];
    const float* wo = (const float*)d_in[7];
    const float* bo = (const float*)d_in[8];

    float* out  = (float*)d_out;
    float* attn = out + (size_t)MTOT * DM;   // tuple order: (out, attn)

    static bool attr_set = false;
    if (!attr_set) {
        cudaFuncSetAttribute(scores_mma_kernel, cudaFuncAttributeMaxDynamicSharedMemorySize, SC_SMEM);
        cudaFuncSetAttribute(pv_mma_kernel,     cudaFuncAttributeMaxDynamicSharedMemorySize, PV_SMEM);
        attr_set = true;
    }

    dim3 g1(8, 32, 3);
    qkv_kernel<<<g1, 256>>>(x, wq, bq, wk, bk, wv, bv);

    dim3 g2(16, 16, 32);
    scores_mma_kernel<<<g2, 256, SC_SMEM>>>(attn);

    dim3 g4(16, 32);
    pv_mma_kernel<<<g4, 256, PV_SMEM>>>(attn);

    dim3 g5(8, 32);
    outproj_kernel<<<g5, 256>>>(wo, bo, out);
}

// round 4
// speedup vs baseline: 1.9935x; 1.4158x over previous
#include <cuda_runtime.h>
#include <cuda_bf16.h>
#include <math.h>
#include <stdint.h>

#define BD   2
#define SEQ  2048
#define DM   1024
#define NH   16
#define DH   64
#define MTOT (BD*SEQ)    // 4096
#define BHT  (BD*NH)     // 32

// ---------------------------------------------------------------------------
// scratch (__device__ globals; allocation-free rule)
// ---------------------------------------------------------------------------
__device__ __nv_bfloat16 g_qh [BHT*SEQ*DH];
__device__ __nv_bfloat16 g_ql [BHT*SEQ*DH];
__device__ __nv_bfloat16 g_kh [BHT*SEQ*DH];
__device__ __nv_bfloat16 g_kl [BHT*SEQ*DH];
__device__ __nv_bfloat16 g_vh [BHT*SEQ*DH];
__device__ __nv_bfloat16 g_vl [BHT*SEQ*DH];
__device__ float g_psum[BHT*SEQ*16];
// bf16 hi/lo splits of inputs/weights (prep kernel)
__device__ __nv_bfloat16 g_xh [MTOT*DM];
__device__ __nv_bfloat16 g_xl [MTOT*DM];
__device__ __nv_bfloat16 g_wqh[DM*DM], g_wql[DM*DM];
__device__ __nv_bfloat16 g_wkh[DM*DM], g_wkl[DM*DM];
__device__ __nv_bfloat16 g_wvh[DM*DM], g_wvl[DM*DM];
__device__ __nv_bfloat16 g_woh[DM*DM], g_wol[DM*DM];
// attention head outputs in [token][dmodel] layout, bf16 hi/lo (for outproj)
__device__ __nv_bfloat16 g_ohh[MTOT*DM];
__device__ __nv_bfloat16 g_ohl[MTOT*DM];

// ---------------------------------------------------------------------------
// warp-MMA helpers (sm_80+ PTX: works on plain sm_103 target)
// ---------------------------------------------------------------------------
__device__ __forceinline__ uint32_t smem_u32(const void* p) {
    uint32_t a;
    asm("{ .reg .u64 t; cvta.to.shared.u64 t, %1; cvt.u32.u64 %0, t; }" : "=r"(a) : "l"(p));
    return a;
}
__device__ __forceinline__ void ldsm4(uint32_t r[4], uint32_t addr) {
    asm volatile("ldmatrix.sync.aligned.m8n8.x4.shared.b16 {%0,%1,%2,%3}, [%4];"
        : "=r"(r[0]), "=r"(r[1]), "=r"(r[2]), "=r"(r[3]) : "r"(addr));
}
__device__ __forceinline__ void ldsm4t(uint32_t r[4], uint32_t addr) {
    asm volatile("ldmatrix.sync.aligned.m8n8.x4.trans.shared.b16 {%0,%1,%2,%3}, [%4];"
        : "=r"(r[0]), "=r"(r[1]), "=r"(r[2]), "=r"(r[3]) : "r"(addr));
}
__device__ __forceinline__ void mma16816(float* c, const uint32_t* a, uint32_t b0, uint32_t b1) {
    asm volatile("mma.sync.aligned.m16n8k16.row.col.f32.bf16.bf16.f32 "
        "{%0,%1,%2,%3}, {%4,%5,%6,%7}, {%8,%9}, {%0,%1,%2,%3};"
        : "+f"(c[0]), "+f"(c[1]), "+f"(c[2]), "+f"(c[3])
        : "r"(a[0]), "r"(a[1]), "r"(a[2]), "r"(a[3]), "r"(b0), "r"(b1));
}
#define SW(o) ((o) ^ (((o) >> 3) & 0x70))

__device__ __forceinline__ uint32_t pack_bf2(__nv_bfloat16 a, __nv_bfloat16 b) {
    return ((uint32_t)__bfloat16_as_ushort(b) << 16) | (uint32_t)__bfloat16_as_ushort(a);
}

// ---------------------------------------------------------------------------
// prep: split fp32 array into bf16 hi/lo
// ---------------------------------------------------------------------------
__global__ __launch_bounds__(256) void split_kernel(
    const float4* __restrict__ src, uint2* __restrict__ dh, uint2* __restrict__ dl, int n4)
{
    int i = blockIdx.x * 256 + threadIdx.x;
    if (i >= n4) return;
    float4 v = src[i];
    __nv_bfloat16 hx=__float2bfloat16(v.x), hy=__float2bfloat16(v.y),
                  hz=__float2bfloat16(v.z), hw=__float2bfloat16(v.w);
    uint2 H; H.x = pack_bf2(hx,hy); H.y = pack_bf2(hz,hw);
    dh[i] = H;
    __nv_bfloat16 lx=__float2bfloat16(v.x-__bfloat162float(hx)),
                  ly=__float2bfloat16(v.y-__bfloat162float(hy)),
                  lz=__float2bfloat16(v.z-__bfloat162float(hz)),
                  lw=__float2bfloat16(v.w-__bfloat162float(hw));
    uint2 L; L.x = pack_bf2(lx,ly); L.y = pack_bf2(lz,lw);
    dl[i] = L;
}

// ---------------------------------------------------------------------------
// Shared GEMM core (bf16-split HMMA): C(128x128) += A(128x64) @ B(64x128)^T'
// A stored [m][k] (128B rows, SW), B stored as [2 halves][64k][64n] (SW),
// consumed via ldmatrix.trans. 8 warps, warp tile 64m x 32n.
// ---------------------------------------------------------------------------
#define GQ_AH   0
#define GQ_AL   16384
#define GQ_BH   32768
#define GQ_BL   49152
#define GQ_FREQ 65536
#define GQ_SMEM (GQ_FREQ + 128)

struct GemmFrag { float acc[4][4][4]; };

__device__ __forceinline__ void gemm_tile_load(
    char* smem, int tid, int m0, int n0, int k0,
    const __nv_bfloat16* Ah, const __nv_bfloat16* Al, int lda,
    const __nv_bfloat16* Bh, const __nv_bfloat16* Bl, int ldb)
{
    #pragma unroll
    for (int i = 0; i < 4; i++) {
        int c = tid + i*256;
        int row = c >> 3, part = c & 7;
        uint32_t off = SW((uint32_t)(row*128 + part*16));
        size_t gi = (size_t)(m0+row)*lda + k0 + part*8;
        *(uint4*)(smem + GQ_AH + off) = *(const uint4*)(Ah + gi);
        *(uint4*)(smem + GQ_AL + off) = *(const uint4*)(Al + gi);
    }
    #pragma unroll
    for (int i = 0; i < 4; i++) {
        int c = tid + i*256;
        int krow = c >> 4, chunk = c & 15;
        int half = chunk >> 3, nl = (chunk & 7) * 8;
        uint32_t off = (uint32_t)(half*8192) + SW((uint32_t)(krow*128 + nl*2));
        size_t gi = (size_t)(k0+krow)*ldb + n0 + chunk*8;
        *(uint4*)(smem + GQ_BH + off) = *(const uint4*)(Bh + gi);
        *(uint4*)(smem + GQ_BL + off) = *(const uint4*)(Bl + gi);
    }
}

__device__ __forceinline__ void gemm_tile_mma(
    uint32_t sb, int lane, int wy, int wx, GemmFrag& f)
{
    const int arow = wy*64 + (lane & 7) + ((lane >> 3) & 1) * 8;
    #pragma unroll
    for (int ks = 0; ks < 4; ks++) {
        uint32_t ah[4][4], al[4][4];
        const uint32_t abase = (uint32_t)(arow*128 + ks*32 + (lane & 16));
        #pragma unroll
        for (int mt = 0; mt < 4; mt++) {
            uint32_t off = SW(abase + mt*16*128);
            ldsm4(ah[mt], sb + GQ_AH + off);
            ldsm4(al[mt], sb + GQ_AL + off);
        }
        #pragma unroll
        for (int np = 0; np < 2; np++) {
            const int g = lane >> 3;
            const int krow = ks*16 + (g & 1)*8 + (lane & 7);
            const int nlg = wx*32 + np*16 + (g >> 1)*8;
            const uint32_t boff = (uint32_t)((nlg >> 6)*8192) + SW((uint32_t)(krow*128 + (nlg & 63)*2));
            uint32_t bH[4], bL[4];
            ldsm4t(bH, sb + GQ_BH + boff);
            ldsm4t(bL, sb + GQ_BL + boff);
            #pragma unroll
            for (int mt = 0; mt < 4; mt++) {
                mma16816(f.acc[mt][np*2+0], ah[mt], bH[0], bH[1]);
                mma16816(f.acc[mt][np*2+0], ah[mt], bL[0], bL[1]);
                mma16816(f.acc[mt][np*2+0], al[mt], bH[0], bH[1]);
                mma16816(f.acc[mt][np*2+1], ah[mt], bH[2], bH[3]);
                mma16816(f.acc[mt][np*2+1], ah[mt], bL[2], bL[3]);
                mma16816(f.acc[mt][np*2+1], al[mt], bH[2], bH[3]);
            }
        }
    }
}

// ---------------------------------------------------------------------------
// QKV projection via HMMA; epilogue: +bias, RoPE (q,k), split bf16 hi/lo
// ---------------------------------------------------------------------------
__global__ __launch_bounds__(256) void qkv_mma_kernel(
    const float* __restrict__ bq, const float* __restrict__ bk, const float* __restrict__ bv)
{
    extern __shared__ __align__(1024) char smem[];
    const uint32_t sb = smem_u32(smem);
    const int tid = threadIdx.x, wid = tid >> 5, lane = tid & 31;
    const int wy = wid >> 2, wx = wid & 3;
    const int n0 = blockIdx.x * 128;
    const int m0 = blockIdx.y * 128;
    const int z = blockIdx.z;

    const __nv_bfloat16* Bh = (z==0) ? g_wqh : (z==1) ? g_wkh : g_wvh;
    const __nv_bfloat16* Bl = (z==0) ? g_wql : (z==1) ? g_wkl : g_wvl;
    const float* bias = (z==0) ? bq : (z==1) ? bk : bv;

    float* s_freq = (float*)(smem + GQ_FREQ);
    if (tid < 32)
        s_freq[tid] = (float)(1.0 / pow(10000.0, (double)(2*tid) / 64.0));

    GemmFrag f;
    #pragma unroll
    for (int a = 0; a < 4; a++)
        #pragma unroll
        for (int b = 0; b < 4; b++)
            #pragma unroll
            for (int c = 0; c < 4; c++) f.acc[a][b][c] = 0.f;

    for (int k0 = 0; k0 < DM; k0 += 64) {
        gemm_tile_load(smem, tid, m0, n0, k0, g_xh, g_xl, DM, Bh, Bl, DM);
        __syncthreads();
        gemm_tile_mma(sb, lane, wy, wx, f);
        __syncthreads();
    }

    __nv_bfloat16* dh = (z==0) ? g_qh : (z==1) ? g_kh : g_vh;
    __nv_bfloat16* dl = (z==0) ? g_ql : (z==1) ? g_kl : g_vl;

    const int gr = lane >> 2, qc = (lane & 3) * 2;
    #pragma unroll
    for (int mt = 0; mt < 4; mt++) {
        #pragma unroll
        for (int h = 0; h < 2; h++) {
            int r = m0 + wy*64 + mt*16 + h*8 + gr;
            int bb = r >> 11;
            int s  = r & 2047;
            #pragma unroll
            for (int nt = 0; nt < 4; nt++) {
                int c = n0 + wx*32 + nt*8 + qc;     // even
                float v0 = f.acc[mt][nt][h*2+0] + bias[c];
                float v1 = f.acc[mt][nt][h*2+1] + bias[c+1];
                float ox = v0, oy = v1;
                if (z < 2) {
                    float fr = s_freq[(c & 63) >> 1];
                    float sn, cs;
                    sincosf((float)s * fr, &sn, &cs);
                    ox = v0*cs - v1*sn;
                    oy = v0*sn + v1*cs;
                }
                int bh = bb*NH + (c >> 6);
                size_t idx = ((size_t)bh*SEQ + s)*DH + (c & 63);
                __nv_bfloat16 h0=__float2bfloat16(ox), h1=__float2bfloat16(oy);
                *(uint32_t*)(dh + idx) = pack_bf2(h0, h1);
                __nv_bfloat16 l0=__float2bfloat16(ox-__bfloat162float(h0)),
                              l1=__float2bfloat16(oy-__bfloat162float(h1));
                *(uint32_t*)(dl + idx) = pack_bf2(l0, l1);
            }
        }
    }
}

// ---------------------------------------------------------------------------
// Output projection via HMMA: out = oh @ Wo + bo (A = g_ohh/g_ohl)
// ---------------------------------------------------------------------------
__global__ __launch_bounds__(256) void outproj_mma_kernel(
    const float* __restrict__ bo, float* __restrict__ out)
{
    extern __shared__ __align__(1024) char smem[];
    const uint32_t sb = smem_u32(smem);
    const int tid = threadIdx.x, wid = tid >> 5, lane = tid & 31;
    const int wy = wid >> 2, wx = wid & 3;
    const int n0 = blockIdx.x * 128;
    const int m0 = blockIdx.y * 128;

    GemmFrag f;
    #pragma unroll
    for (int a = 0; a < 4; a++)
        #pragma unroll
        for (int b = 0; b < 4; b++)
            #pragma unroll
            for (int c = 0; c < 4; c++) f.acc[a][b][c] = 0.f;

    for (int k0 = 0; k0 < DM; k0 += 64) {
        gemm_tile_load(smem, tid, m0, n0, k0, g_ohh, g_ohl, DM, g_woh, g_wol, DM);
        __syncthreads();
        gemm_tile_mma(sb, lane, wy, wx, f);
        __syncthreads();
    }

    const int gr = lane >> 2, qc = (lane & 3) * 2;
    #pragma unroll
    for (int mt = 0; mt < 4; mt++) {
        #pragma unroll
        for (int h = 0; h < 2; h++) {
            int r = m0 + wy*64 + mt*16 + h*8 + gr;
            #pragma unroll
            for (int nt = 0; nt < 4; nt++) {
                int c = n0 + wx*32 + nt*8 + qc;
                float2 o;
                o.x = f.acc[mt][nt][h*2+0] + bo[c];
                o.y = f.acc[mt][nt][h*2+1] + bo[c+1];
                *(float2*)(out + (size_t)r*DM + c) = o;
            }
        }
    }
}

// ---------------------------------------------------------------------------
// scores (HMMA bf16-split): block 128(M) x 128(N), K=64.
// ---------------------------------------------------------------------------
#define SC_QH   0
#define SC_QL   16384
#define SC_KH   32768
#define SC_KL   49152
#define SC_SROW 65536
#define SC_SMEM (SC_SROW + 128*4*4)

__global__ __launch_bounds__(256) void scores_mma_kernel(float* __restrict__ attn)
{
    extern __shared__ __align__(1024) char smem[];
    const uint32_t sb = smem_u32(smem);
    const int tid = threadIdx.x, wid = tid >> 5, lane = tid & 31;
    const int wy = wid >> 2, wx = wid & 3;
    const int nblk = blockIdx.x;
    const int n0 = nblk * 128;
    const int m0 = blockIdx.y * 128;
    const int bh = blockIdx.z;

    {
        const uint4* qh = (const uint4*)(g_qh + ((size_t)bh*SEQ + m0)*DH);
        const uint4* ql = (const uint4*)(g_ql + ((size_t)bh*SEQ + m0)*DH);
        const uint4* kh = (const uint4*)(g_kh + ((size_t)bh*SEQ + n0)*DH);
        const uint4* kl = (const uint4*)(g_kl + ((size_t)bh*SEQ + n0)*DH);
        #pragma unroll
        for (int i = 0; i < 4; i++) {
            int c = tid + i*256;
            int row = c >> 3, part = c & 7;
            uint32_t off = SW((uint32_t)(row*128 + part*16));
            *(uint4*)(smem + SC_QH + off) = qh[row*8 + part];
            *(uint4*)(smem + SC_QL + off) = ql[row*8 + part];
            *(uint4*)(smem + SC_KH + off) = kh[row*8 + part];
            *(uint4*)(smem + SC_KL + off) = kl[row*8 + part];
        }
    }
    __syncthreads();

    float acc[4][4][4];
    #pragma unroll
    for (int a = 0; a < 4; a++)
        #pragma unroll
        for (int b = 0; b < 4; b++)
            #pragma unroll
            for (int c = 0; c < 4; c++) acc[a][b][c] = 0.f;

    const int arow = wy*64 + (lane & 7) + ((lane >> 3) & 1) * 8;
    #pragma unroll
    for (int ks = 0; ks < 4; ks++) {
        uint32_t ah[4][4], al[4][4];
        const uint32_t abase = (uint32_t)(arow*128 + ks*32 + (lane & 16));
        #pragma unroll
        for (int mt = 0; mt < 4; mt++) {
            uint32_t off = SW(abase + mt*16*128);
            ldsm4(ah[mt], sb + SC_QH + off);
            ldsm4(al[mt], sb + SC_QL + off);
        }
        #pragma unroll
        for (int np = 0; np < 2; np++) {
            const int g = lane >> 3;
            const int nrow = wx*32 + np*16 + (g >> 1)*8 + (lane & 7);
            const uint32_t boff = SW((uint32_t)(nrow*128 + ks*32 + (g & 1)*16));
            uint32_t bH[4], bL[4];
            ldsm4(bH, sb + SC_KH + boff);
            ldsm4(bL, sb + SC_KL + boff);
            #pragma unroll
            for (int mt = 0; mt < 4; mt++) {
                mma16816(acc[mt][np*2+0], ah[mt], bH[0], bH[1]);
                mma16816(acc[mt][np*2+0], ah[mt], bL[0], bL[1]);
                mma16816(acc[mt][np*2+0], al[mt], bH[0], bH[1]);
                mma16816(acc[mt][np*2+1], ah[mt], bH[2], bH[3]);
                mma16816(acc[mt][np*2+1], ah[mt], bL[2], bL[3]);
                mma16816(acc[mt][np*2+1], al[mt], bH[2], bH[3]);
            }
        }
    }

    const int gr = lane >> 2, qc = (lane & 3) * 2;
    float* srw = (float*)(smem + SC_SROW);
    #pragma unroll
    for (int mt = 0; mt < 4; mt++) {
        #pragma unroll
        for (int h = 0; h < 2; h++) {
            int rl = wy*64 + mt*16 + h*8 + gr;
            float* arow_p = attn + ((size_t)bh*SEQ + m0 + rl)*SEQ + n0 + wx*32;
            float rs = 0.f;
            #pragma unroll
            for (int nt = 0; nt < 4; nt++) {
                float e0 = __expf(acc[mt][nt][h*2+0] * 0.125f);
                float e1 = __expf(acc[mt][nt][h*2+1] * 0.125f);
                rs += e0 + e1;
                *(float2*)(arow_p + nt*8 + qc) = make_float2(e0, e1);
            }
            rs += __shfl_xor_sync(0xffffffffu, rs, 1);
            rs += __shfl_xor_sync(0xffffffffu, rs, 2);
            if ((lane & 3) == 0) srw[rl*4 + wx] = rs;
        }
    }
    __syncthreads();
    if (tid < 128) {
        float s = srw[tid*4+0] + srw[tid*4+1] + srw[tid*4+2] + srw[tid*4+3];
        g_psum[((size_t)bh*SEQ + m0 + tid)*16 + nblk] = s;
    }
}

// ---------------------------------------------------------------------------
// pv (HMMA bf16-split): normalizes P in-flight (writes normalized attn back),
// accumulates P@V; epilogue writes bf16 hi/lo into [token][dmodel] for outproj.
// ---------------------------------------------------------------------------
#define PV_INV  0
#define PV_PH   1024
#define PV_PL   (PV_PH + 16384)
#define PV_VH   (PV_PL + 16384)
#define PV_VL   (PV_VH + 8192)
#define PV_SMEM (PV_VL + 8192)

__global__ __launch_bounds__(256) void pv_mma_kernel(float* __restrict__ attn)
{
    extern __shared__ __align__(1024) char smem[];
    const uint32_t sb = smem_u32(smem);
    const int tid = threadIdx.x, wid = tid >> 5, lane = tid & 31;
    const int wy = wid >> 1, wx = wid & 1;
    const int m0 = blockIdx.x * 128;
    const int bh = blockIdx.y;

    float* s_inv = (float*)(smem + PV_INV);
    if (tid < 128) {
        const float* ps = g_psum + ((size_t)bh*SEQ + m0 + tid)*16;
        float s = 0.f;
        #pragma unroll
        for (int j = 0; j < 16; j++) s += ps[j];
        s_inv[tid] = 1.f / s;
    }
    __syncthreads();

    float acc[2][4][4];
    #pragma unroll
    for (int a = 0; a < 2; a++)
        #pragma unroll
        for (int b = 0; b < 4; b++)
            #pragma unroll
            for (int c = 0; c < 4; c++) acc[a][b][c] = 0.f;

    const int prow0 = tid >> 4;
    const int col4  = (tid & 15) * 4;

    for (int kt = 0; kt < 32; kt++) {
        const int k0 = kt * 64;
        #pragma unroll
        for (int it = 0; it < 8; it++) {
            int row = prow0 + it*16;
            float* gp = attn + ((size_t)bh*SEQ + m0 + row)*SEQ + k0 + col4;
            float4 p = *(float4*)gp;
            float inv = s_inv[row];
            p.x *= inv; p.y *= inv; p.z *= inv; p.w *= inv;
            *(float4*)gp = p;
            __nv_bfloat16 hx=__float2bfloat16(p.x), hy=__float2bfloat16(p.y),
                          hz=__float2bfloat16(p.z), hw=__float2bfloat16(p.w);
            uint2 H; H.x = pack_bf2(hx,hy); H.y = pack_bf2(hz,hw);
            __nv_bfloat16 lx=__float2bfloat16(p.x-__bfloat162float(hx)),
                          ly=__float2bfloat16(p.y-__bfloat162float(hy)),
                          lz=__float2bfloat16(p.z-__bfloat162float(hz)),
                          lw=__float2bfloat16(p.w-__bfloat162float(hw));
            uint2 L; L.x = pack_bf2(lx,ly); L.y = pack_bf2(lz,lw);
            uint32_t off = SW((uint32_t)(row*128 + col4*2));
            *(uint2*)(smem + PV_PH + off) = H;
            *(uint2*)(smem + PV_PL + off) = L;
        }
        #pragma unroll
        for (int i = 0; i < 2; i++) {
            int c = tid + i*256;
            int srow = c >> 3, part = c & 7;
            uint32_t off = SW((uint32_t)(srow*128 + part*16));
            size_t gi = ((size_t)bh*SEQ + k0 + srow)*DH + part*8;
            *(uint4*)(smem + PV_VH + off) = *(const uint4*)(g_vh + gi);
            *(uint4*)(smem + PV_VL + off) = *(const uint4*)(g_vl + gi);
        }
        __syncthreads();

        const int arow = wy*32 + (lane & 7) + ((lane >> 3) & 1) * 8;
        #pragma unroll
        for (int ks = 0; ks < 4; ks++) {
            uint32_t ah[2][4], al[2][4];
            const uint32_t abase = (uint32_t)(arow*128 + ks*32 + (lane & 16));
            #pragma unroll
            for (int mt = 0; mt < 2; mt++) {
                uint32_t off = SW(abase + mt*16*128);
                ldsm4(ah[mt], sb + PV_PH + off);
                ldsm4(al[mt], sb + PV_PL + off);
            }
            #pragma unroll
            for (int np = 0; np < 2; np++) {
                const int g = lane >> 3;
                const int krow = ks*16 + (g & 1)*8 + (lane & 7);
                const int ncol = wx*32 + np*16 + (g >> 1)*8;
                const uint32_t boff = SW((uint32_t)(krow*128 + ncol*2));
                uint32_t bH[4], bL[4];
                ldsm4t(bH, sb + PV_VH + boff);
                ldsm4t(bL, sb + PV_VL + boff);
                #pragma unroll
                for (int mt = 0; mt < 2; mt++) {
                    mma16816(acc[mt][np*2+0], ah[mt], bH[0], bH[1]);
                    mma16816(acc[mt][np*2+0], ah[mt], bL[0], bL[1]);
                    mma16816(acc[mt][np*2+0], al[mt], bH[0], bH[1]);
                    mma16816(acc[mt][np*2+1], ah[mt], bH[2], bH[3]);
                    mma16816(acc[mt][np*2+1], ah[mt], bL[2], bL[3]);
                    mma16816(acc[mt][np*2+1], al[mt], bH[2], bH[3]);
                }
            }
        }
        __syncthreads();
    }

    // epilogue: write bf16 hi/lo head outputs into [token][dmodel]
    const int gr = lane >> 2, qc = (lane & 3) * 2;
    const int bb = bh >> 4, hh = bh & 15;
    #pragma unroll
    for (int mt = 0; mt < 2; mt++) {
        #pragma unroll
        for (int h = 0; h < 2; h++) {
            int rl = wy*32 + mt*16 + h*8 + gr;
            size_t token = (size_t)bb*SEQ + m0 + rl;
            #pragma unroll
            for (int nt = 0; nt < 4; nt++) {
                int col = hh*64 + wx*32 + nt*8 + qc;
                float v0 = acc[mt][nt][h*2+0];
                float v1 = acc[mt][nt][h*2+1];
                __nv_bfloat16 h0=__float2bfloat16(v0), h1=__float2bfloat16(v1);
                *(uint32_t*)(g_ohh + token*DM + col) = pack_bf2(h0, h1);
                __nv_bfloat16 l0=__float2bfloat16(v0-__bfloat162float(h0)),
                              l1=__float2bfloat16(v1-__bfloat162float(h1));
                *(uint32_t*)(g_ohl + token*DM + col) = pack_bf2(l0, l1);
            }
        }
    }
}

// ---------------------------------------------------------------------------
extern "C" void kernel_launch(void* const* d_in, const int* in_sizes, int n_in,
                              void* d_out, int out_size)
{
    const float* x  = (const float*)d_in[0];
    const float* wq = (const float*)d_in[1];
    const float* bq = (const float*)d_in[2];
    const float* wk = (const float*)d_in[3];
    const float* bk = (const float*)d_in[4];
    const float* wv = (const float*)d_in[5];
    const float* bv = (const float*)d_in[6];
    const float* wo = (const float*)d_in[7];
    const float* bo = (const float*)d_in[8];

    float* out  = (float*)d_out;
    float* attn = out + (size_t)MTOT * DM;   // tuple order: (out, attn)

    static bool attr_set = false;
    if (!attr_set) {
        cudaFuncSetAttribute(qkv_mma_kernel,     cudaFuncAttributeMaxDynamicSharedMemorySize, GQ_SMEM);
        cudaFuncSetAttribute(outproj_mma_kernel, cudaFuncAttributeMaxDynamicSharedMemorySize, GQ_SMEM);
        cudaFuncSetAttribute(scores_mma_kernel,  cudaFuncAttributeMaxDynamicSharedMemorySize, SC_SMEM);
        cudaFuncSetAttribute(pv_mma_kernel,      cudaFuncAttributeMaxDynamicSharedMemorySize, PV_SMEM);
        attr_set = true;
    }

    // device-global scratch addresses (host-side symbol -> device ptr not needed;
    // split kernels write via __device__ symbols directly)
    {
        __nv_bfloat16 *xh, *xl, *wqh, *wql, *wkh, *wkl, *wvh, *wvl, *woh, *wol;
        cudaGetSymbolAddress((void**)&xh,  g_xh);  cudaGetSymbolAddress((void**)&xl,  g_xl);
        cudaGetSymbolAddress((void**)&wqh, g_wqh); cudaGetSymbolAddress((void**)&wql, g_wql);
        cudaGetSymbolAddress((void**)&wkh, g_wkh); cudaGetSymbolAddress((void**)&wkl, g_wkl);
        cudaGetSymbolAddress((void**)&wvh, g_wvh); cudaGetSymbolAddress((void**)&wvl, g_wvl);
        cudaGetSymbolAddress((void**)&woh, g_woh); cudaGetSymbolAddress((void**)&wol, g_wol);

        int n4x = MTOT*DM/4, n4w = DM*DM/4;
        split_kernel<<<(n4x+255)/256, 256>>>((const float4*)x,  (uint2*)xh,  (uint2*)xl,  n4x);
        split_kernel<<<(n4w+255)/256, 256>>>((const float4*)wq, (uint2*)wqh, (uint2*)wql, n4w);
        split_kernel<<<(n4w+255)/256, 256>>>((const float4*)wk, (uint2*)wkh, (uint2*)wkl, n4w);
        split_kernel<<<(n4w+255)/256, 256>>>((const float4*)wv, (uint2*)wvh, (uint2*)wvl, n4w);
        split_kernel<<<(n4w+255)/256, 256>>>((const float4*)wo, (uint2*)woh, (uint2*)wol, n4w);
    }

    dim3 g1(8, 32, 3);
    qkv_mma_kernel<<<g1, 256, GQ_SMEM>>>(bq, bk, bv);

    dim3 g2(16, 16, 32);
    scores_mma_kernel<<<g2, 256, SC_SMEM>>>(attn);

    dim3 g4(16, 32);
    pv_mma_kernel<<<g4, 256, PV_SMEM>>>(attn);

    dim3 g5(8, 32);
    outproj_mma_kernel<<<g5, 256, GQ_SMEM>>>(bo, out);
}

// round 5
// speedup vs baseline: 3.5486x; 1.7801x over previous
#include <cuda_runtime.h>
#include <cuda_bf16.h>
#include <cuda_fp16.h>
#include <math.h>
#include <stdint.h>

#define BD   2
#define SEQ  2048
#define DM   1024
#define NH   16
#define DH   64
#define MTOT (BD*SEQ)    // 4096
#define BHT  (BD*NH)     // 32

// ---------------------------------------------------------------------------
// scratch (__device__ globals; allocation-free rule)
// ---------------------------------------------------------------------------
__device__ __half g_q  [BHT*SEQ*DH];     // RoPE'd Q, fp16 [bh][s][d]
__device__ __half g_k  [BHT*SEQ*DH];     // RoPE'd K
__device__ __half g_v  [BHT*SEQ*DH];     // V
__device__ __half g_xh [MTOT*DM];        // x in fp16
__device__ __half g_wq [DM*DM], g_wk[DM*DM], g_wv[DM*DM], g_wo[DM*DM];
__device__ __half g_ohf[MTOT*DM];        // head outputs [token][dmodel] fp16
__device__ float  g_inv[BHT*SEQ];        // per-row 1/rowsum

// ---------------------------------------------------------------------------
// warp-MMA helpers (sm_80+ PTX, plain sm_103 target)
// ---------------------------------------------------------------------------
__device__ __forceinline__ uint32_t smem_u32(const void* p) {
    uint32_t a;
    asm("{ .reg .u64 t; cvta.to.shared.u64 t, %1; cvt.u32.u64 %0, t; }" : "=r"(a) : "l"(p));
    return a;
}
__device__ __forceinline__ void ldsm4(uint32_t r[4], uint32_t addr) {
    asm volatile("ldmatrix.sync.aligned.m8n8.x4.shared.b16 {%0,%1,%2,%3}, [%4];"
        : "=r"(r[0]), "=r"(r[1]), "=r"(r[2]), "=r"(r[3]) : "r"(addr));
}
__device__ __forceinline__ void ldsm4t(uint32_t r[4], uint32_t addr) {
    asm volatile("ldmatrix.sync.aligned.m8n8.x4.trans.shared.b16 {%0,%1,%2,%3}, [%4];"
        : "=r"(r[0]), "=r"(r[1]), "=r"(r[2]), "=r"(r[3]) : "r"(addr));
}
__device__ __forceinline__ void mmah(float* c, const uint32_t* a, uint32_t b0, uint32_t b1) {
    asm volatile("mma.sync.aligned.m16n8k16.row.col.f32.f16.f16.f32 "
        "{%0,%1,%2,%3}, {%4,%5,%6,%7}, {%8,%9}, {%0,%1,%2,%3};"
        : "+f"(c[0]), "+f"(c[1]), "+f"(c[2]), "+f"(c[3])
        : "r"(a[0]), "r"(a[1]), "r"(a[2]), "r"(a[3]), "r"(b0), "r"(b1));
}
__device__ __forceinline__ void cp16(uint32_t dst, const void* src) {
    asm volatile("cp.async.cg.shared.global [%0], [%1], 16;" :: "r"(dst), "l"(src));
}
#define CP_COMMIT() asm volatile("cp.async.commit_group;" ::: "memory")
#define CP_WAIT0()  asm volatile("cp.async.wait_group 0;" ::: "memory")
#define SW(o) ((o) ^ (((o) >> 3) & 0x70))

__device__ __forceinline__ uint32_t h2pack(float a, float b) {
    __half2 h = __floats2half2_rn(a, b);
    return *(uint32_t*)&h;
}

// ---------------------------------------------------------------------------
// prep: fp32 -> fp16
// ---------------------------------------------------------------------------
__global__ __launch_bounds__(256) void tohalf_kernel(
    const float4* __restrict__ src, uint2* __restrict__ dst, int n4)
{
    int i = blockIdx.x * 256 + threadIdx.x;
    if (i >= n4) return;
    float4 v = src[i];
    uint2 o;
    o.x = h2pack(v.x, v.y);
    o.y = h2pack(v.z, v.w);
    dst[i] = o;
}

// ---------------------------------------------------------------------------
// GEMM core (single fp16 HMMA): C(128x128) = A(128xK) @ B(KxN), K-tiles of 64
// A [m][k] 128B rows; B stored as [2 halves][64k][64n], both SW-swizzled.
// 8 warps, warp tile 64m x 32n.
// ---------------------------------------------------------------------------
#define GQ_A    0
#define GQ_B    16384
#define GQ_FREQ 32768
#define GQ_SMEM (GQ_FREQ + 128)

__device__ __forceinline__ void gemm_tile_load_h(
    char* smem, int tid, int m0, int n0, int k0,
    const __half* A, int lda, const __half* B, int ldb)
{
    #pragma unroll
    for (int i = 0; i < 4; i++) {
        int c = tid + i*256;
        int row = c >> 3, part = c & 7;
        uint32_t off = SW((uint32_t)(row*128 + part*16));
        *(uint4*)(smem + GQ_A + off) = *(const uint4*)(A + (size_t)(m0+row)*lda + k0 + part*8);
    }
    #pragma unroll
    for (int i = 0; i < 4; i++) {
        int c = tid + i*256;
        int krow = c >> 4, chunk = c & 15;
        int half_ = chunk >> 3, nl = (chunk & 7) * 8;
        uint32_t off = (uint32_t)(half_*8192) + SW((uint32_t)(krow*128 + nl*2));
        *(uint4*)(smem + GQ_B + off) = *(const uint4*)(B + (size_t)(k0+krow)*ldb + n0 + chunk*8);
    }
}

__device__ __forceinline__ void gemm_tile_mma_h(
    uint32_t sb, int lane, int wy, int wx, float acc[4][4][4])
{
    const int g = lane >> 3;
    const int arow = wy*64 + (lane & 7) + ((lane >> 3) & 1) * 8;
    #pragma unroll
    for (int ks = 0; ks < 4; ks++) {
        uint32_t a[4][4];
        const uint32_t abase = (uint32_t)(arow*128 + ks*32 + (lane & 16));
        #pragma unroll
        for (int mt = 0; mt < 4; mt++)
            ldsm4(a[mt], sb + GQ_A + SW(abase + mt*16*128));
        #pragma unroll
        for (int np = 0; np < 2; np++) {
            const int krow = ks*16 + (g & 1)*8 + (lane & 7);
            const int nlg = wx*32 + np*16 + (g >> 1)*8;
            const uint32_t boff = (uint32_t)((nlg >> 6)*8192) + SW((uint32_t)(krow*128 + (nlg & 63)*2));
            uint32_t b[4];
            ldsm4t(b, sb + GQ_B + boff);
            #pragma unroll
            for (int mt = 0; mt < 4; mt++) {
                mmah(acc[mt][np*2+0], a[mt], b[0], b[1]);
                mmah(acc[mt][np*2+1], a[mt], b[2], b[3]);
            }
        }
    }
}

// ---------------------------------------------------------------------------
// QKV projection; epilogue: +bias, RoPE (q,k), store fp16 [bh][s][d]
// ---------------------------------------------------------------------------
__global__ __launch_bounds__(256) void qkv_mma_kernel(
    const float* __restrict__ bq, const float* __restrict__ bk, const float* __restrict__ bv)
{
    extern __shared__ __align__(1024) char smem[];
    const uint32_t sb = smem_u32(smem);
    const int tid = threadIdx.x, wid = tid >> 5, lane = tid & 31;
    const int wy = wid >> 2, wx = wid & 3;
    const int n0 = blockIdx.x * 128;
    const int m0 = blockIdx.y * 128;
    const int z = blockIdx.z;

    const __half* B    = (z==0) ? g_wq : (z==1) ? g_wk : g_wv;
    const float* bias  = (z==0) ? bq   : (z==1) ? bk   : bv;

    float* s_freq = (float*)(smem + GQ_FREQ);
    if (tid < 32)
        s_freq[tid] = (float)(1.0 / pow(10000.0, (double)(2*tid) / 64.0));

    float acc[4][4][4];
    #pragma unroll
    for (int a = 0; a < 4; a++)
        #pragma unroll
        for (int b = 0; b < 4; b++)
            #pragma unroll
            for (int c = 0; c < 4; c++) acc[a][b][c] = 0.f;

    for (int k0 = 0; k0 < DM; k0 += 64) {
        gemm_tile_load_h(smem, tid, m0, n0, k0, g_xh, DM, B, DM);
        __syncthreads();
        gemm_tile_mma_h(sb, lane, wy, wx, acc);
        __syncthreads();
    }

    __half* dst = (z==0) ? g_q : (z==1) ? g_k : g_v;
    const int gr = lane >> 2, qc = (lane & 3) * 2;
    #pragma unroll
    for (int mt = 0; mt < 4; mt++) {
        #pragma unroll
        for (int h = 0; h < 2; h++) {
            int r = m0 + wy*64 + mt*16 + h*8 + gr;
            int bb = r >> 11;
            int s  = r & 2047;
            #pragma unroll
            for (int nt = 0; nt < 4; nt++) {
                int c = n0 + wx*32 + nt*8 + qc;   // even col
                float v0 = acc[mt][nt][h*2+0] + bias[c];
                float v1 = acc[mt][nt][h*2+1] + bias[c+1];
                float ox = v0, oy = v1;
                if (z < 2) {
                    float fr = s_freq[(c & 63) >> 1];
                    float sn, cs;
                    sincosf((float)s * fr, &sn, &cs);
                    ox = v0*cs - v1*sn;
                    oy = v0*sn + v1*cs;
                }
                int bh = bb*NH + (c >> 6);
                size_t idx = ((size_t)bh*SEQ + s)*DH + (c & 63);
                *(uint32_t*)(dst + idx) = h2pack(ox, oy);
            }
        }
    }
}

// ---------------------------------------------------------------------------
// Fused attention: per block (128 m-rows, one bh). Loop over 32 chunks of 64
// keys: S = QK^T (HMMA), e = exp(S/8) -> unnormalized attn write + rowsum,
// P fragments (fp16, from registers) -> PV HMMA accumulation.
// 8 warps, warp = 16 m-rows x full 64-chunk.
// ---------------------------------------------------------------------------
#define FA_SQ   0
#define FA_K0   16384
#define FA_K1   24576
#define FA_V0   32768
#define FA_V1   40960
#define FA_SMEM 49152

__device__ __forceinline__ void fa_prefetch(uint32_t sb, int buf, int bh, int k0, int tid)
{
    const __half* kp = g_k + ((size_t)bh*SEQ + k0)*DH;
    const __half* vp = g_v + ((size_t)bh*SEQ + k0)*DH;
    const uint32_t kb = sb + (buf ? FA_K1 : FA_K0);
    const uint32_t vb = sb + (buf ? FA_V1 : FA_V0);
    #pragma unroll
    for (int i = 0; i < 2; i++) {
        int c = tid + i*256;
        int row = c >> 3, part = c & 7;
        uint32_t off = SW((uint32_t)(row*128 + part*16));
        cp16(kb + off, kp + (size_t)row*DH + part*8);
        cp16(vb + off, vp + (size_t)row*DH + part*8);
    }
}

__global__ __launch_bounds__(256) void fattn_kernel(float* __restrict__ attn)
{
    extern __shared__ __align__(1024) char smem[];
    const uint32_t sb = smem_u32(smem);
    const int tid = threadIdx.x, wid = tid >> 5, lane = tid & 31;
    const int m0 = blockIdx.x * 128;
    const int bh = blockIdx.y;
    const int g = lane >> 3, gr = lane >> 2, qc = (lane & 3) * 2;

    // load Q tile (128 x 64 fp16, swizzled)
    {
        const uint4* qsrc = (const uint4*)(g_q + ((size_t)bh*SEQ + m0)*DH);
        #pragma unroll
        for (int i = 0; i < 4; i++) {
            int c = tid + i*256;
            int row = c >> 3, part = c & 7;
            *(uint4*)(smem + FA_SQ + SW((uint32_t)(row*128 + part*16))) = qsrc[row*8 + part];
        }
    }
    fa_prefetch(sb, 0, bh, 0, tid);
    CP_COMMIT();
    __syncthreads();

    // per-warp persistent Q fragments (16 m-rows x 64 k)
    uint32_t qf[4][4];
    {
        const int arow = wid*16 + (lane & 7) + ((lane >> 3) & 1)*8;
        #pragma unroll
        for (int ks = 0; ks < 4; ks++)
            ldsm4(qf[ks], sb + FA_SQ + SW((uint32_t)(arow*128 + ks*32 + (lane & 16))));
    }

    float o[8][4];
    #pragma unroll
    for (int t = 0; t < 8; t++)
        #pragma unroll
        for (int j = 0; j < 4; j++) o[t][j] = 0.f;
    float rs0 = 0.f, rs1 = 0.f;

    const int row0 = m0 + wid*16 + gr;
    float* arow0 = attn + ((size_t)bh*SEQ + row0)*SEQ;
    float* arow1 = arow0 + 8*SEQ;

    for (int kt = 0; kt < 32; kt++) {
        CP_WAIT0();
        __syncthreads();
        if (kt < 31) { fa_prefetch(sb, (kt+1) & 1, bh, (kt+1)*64, tid); CP_COMMIT(); }

        const uint32_t kb = sb + ((kt & 1) ? FA_K1 : FA_K0);
        const uint32_t vb = sb + ((kt & 1) ? FA_V1 : FA_V0);

        // scores: S(16m x 64n) = Q @ K^T
        float S[8][4];
        #pragma unroll
        for (int t = 0; t < 8; t++)
            #pragma unroll
            for (int j = 0; j < 4; j++) S[t][j] = 0.f;

        #pragma unroll
        for (int np = 0; np < 4; np++) {
            const int nrow = np*16 + (g >> 1)*8 + (lane & 7);
            #pragma unroll
            for (int ks = 0; ks < 4; ks++) {
                uint32_t bK[4];
                ldsm4(bK, kb + SW((uint32_t)(nrow*128 + ks*32 + (g & 1)*16)));
                mmah(S[np*2+0], qf[ks], bK[0], bK[1]);
                mmah(S[np*2+1], qf[ks], bK[2], bK[3]);
            }
        }

        // exp + rowsum + unnormalized attn write
        #pragma unroll
        for (int t = 0; t < 8; t++) {
            S[t][0] = __expf(S[t][0] * 0.125f);
            S[t][1] = __expf(S[t][1] * 0.125f);
            S[t][2] = __expf(S[t][2] * 0.125f);
            S[t][3] = __expf(S[t][3] * 0.125f);
            rs0 += S[t][0] + S[t][1];
            rs1 += S[t][2] + S[t][3];
            int col = kt*64 + t*8 + qc;
            *(float2*)(arow0 + col) = make_float2(S[t][0], S[t][1]);
            *(float2*)(arow1 + col) = make_float2(S[t][2], S[t][3]);
        }

        // PV: O(16m x 64d) += P(fp16 from regs) @ V
        #pragma unroll
        for (int kk = 0; kk < 4; kk++) {
            uint32_t aP[4];
            aP[0] = h2pack(S[2*kk  ][0], S[2*kk  ][1]);
            aP[1] = h2pack(S[2*kk  ][2], S[2*kk  ][3]);
            aP[2] = h2pack(S[2*kk+1][0], S[2*kk+1][1]);
            aP[3] = h2pack(S[2*kk+1][2], S[2*kk+1][3]);
            const int krow = kk*16 + (g & 1)*8 + (lane & 7);
            #pragma unroll
            for (int np = 0; np < 4; np++) {
                const int ncol = np*16 + (g >> 1)*8;
                uint32_t bV[4];
                ldsm4t(bV, vb + SW((uint32_t)(krow*128 + ncol*2)));
                mmah(o[np*2+0], aP, bV[0], bV[1]);
                mmah(o[np*2+1], aP, bV[2], bV[3]);
            }
        }
    }

    // rowsum reduce within quad, broadcast
    rs0 += __shfl_xor_sync(0xffffffffu, rs0, 1);
    rs0 += __shfl_xor_sync(0xffffffffu, rs0, 2);
    rs1 += __shfl_xor_sync(0xffffffffu, rs1, 1);
    rs1 += __shfl_xor_sync(0xffffffffu, rs1, 2);
    float inv0 = 1.f / rs0;
    float inv1 = 1.f / rs1;

    if ((lane & 3) == 0) {
        g_inv[(size_t)bh*SEQ + row0]     = inv0;
        g_inv[(size_t)bh*SEQ + row0 + 8] = inv1;
    }

    // write normalized head outputs (fp16) into [token][dmodel]
    const int bb = bh >> 4, hh = bh & 15;
    __half* o0 = g_ohf + ((size_t)bb*SEQ + row0)*DM + hh*64;
    __half* o1 = o0 + 8*DM;
    #pragma unroll
    for (int t = 0; t < 8; t++) {
        *(uint32_t*)(o0 + t*8 + qc) = h2pack(o[t][0]*inv0, o[t][1]*inv0);
        *(uint32_t*)(o1 + t*8 + qc) = h2pack(o[t][2]*inv1, o[t][3]*inv1);
    }
}

// ---------------------------------------------------------------------------
// normalize attn in place: attn[row][:] *= g_inv[row]
// ---------------------------------------------------------------------------
__global__ __launch_bounds__(256) void norm_attn_kernel(float* __restrict__ attn)
{
    const size_t row = blockIdx.x;
    const float inv = g_inv[row];
    float4* p = (float4*)(attn + row*SEQ);
    const int tid = threadIdx.x;
    float4 a = p[tid];
    a.x *= inv; a.y *= inv; a.z *= inv; a.w *= inv;
    p[tid] = a;
    float4 b = p[tid + 256];
    b.x *= inv; b.y *= inv; b.z *= inv; b.w *= inv;
    p[tid + 256] = b;
}

// ---------------------------------------------------------------------------
// Output projection: out = oh @ Wo + bo
// ---------------------------------------------------------------------------
__global__ __launch_bounds__(256) void outproj_mma_kernel(
    const float* __restrict__ bo, float* __restrict__ out)
{
    extern __shared__ __align__(1024) char smem[];
    const uint32_t sb = smem_u32(smem);
    const int tid = threadIdx.x, wid = tid >> 5, lane = tid & 31;
    const int wy = wid >> 2, wx = wid & 3;
    const int n0 = blockIdx.x * 128;
    const int m0 = blockIdx.y * 128;

    float acc[4][4][4];
    #pragma unroll
    for (int a = 0; a < 4; a++)
        #pragma unroll
        for (int b = 0; b < 4; b++)
            #pragma unroll
            for (int c = 0; c < 4; c++) acc[a][b][c] = 0.f;

    for (int k0 = 0; k0 < DM; k0 += 64) {
        gemm_tile_load_h(smem, tid, m0, n0, k0, g_ohf, DM, g_wo, DM);
        __syncthreads();
        gemm_tile_mma_h(sb, lane, wy, wx, acc);
        __syncthreads();
    }

    const int gr = lane >> 2, qc = (lane & 3) * 2;
    #pragma unroll
    for (int mt = 0; mt < 4; mt++) {
        #pragma unroll
        for (int h = 0; h < 2; h++) {
            int r = m0 + wy*64 + mt*16 + h*8 + gr;
            #pragma unroll
            for (int nt = 0; nt < 4; nt++) {
                int c = n0 + wx*32 + nt*8 + qc;
                float2 oo;
                oo.x = acc[mt][nt][h*2+0] + bo[c];
                oo.y = acc[mt][nt][h*2+1] + bo[c+1];
                *(float2*)(out + (size_t)r*DM + c) = oo;
            }
        }
    }
}

// ---------------------------------------------------------------------------
extern "C" void kernel_launch(void* const* d_in, const int* in_sizes, int n_in,
                              void* d_out, int out_size)
{
    const float* x  = (const float*)d_in[0];
    const float* wq = (const float*)d_in[1];
    const float* bq = (const float*)d_in[2];
    const float* wk = (const float*)d_in[3];
    const float* bk = (const float*)d_in[4];
    const float* wv = (const float*)d_in[5];
    const float* bv = (const float*)d_in[6];
    const float* wo = (const float*)d_in[7];
    const float* bo = (const float*)d_in[8];

    float* out  = (float*)d_out;
    float* attn = out + (size_t)MTOT * DM;   // tuple order: (out, attn)

    static bool attr_set = false;
    if (!attr_set) {
        cudaFuncSetAttribute(qkv_mma_kernel,     cudaFuncAttributeMaxDynamicSharedMemorySize, GQ_SMEM);
        cudaFuncSetAttribute(outproj_mma_kernel, cudaFuncAttributeMaxDynamicSharedMemorySize, GQ_SMEM);
        cudaFuncSetAttribute(fattn_kernel,       cudaFuncAttributeMaxDynamicSharedMemorySize, FA_SMEM);
        attr_set = true;
    }

    {
        __half *xh, *wqh, *wkh, *wvh, *woh;
        cudaGetSymbolAddress((void**)&xh,  g_xh);
        cudaGetSymbolAddress((void**)&wqh, g_wq);
        cudaGetSymbolAddress((void**)&wkh, g_wk);
        cudaGetSymbolAddress((void**)&wvh, g_wv);
        cudaGetSymbolAddress((void**)&woh, g_wo);

        int n4x = MTOT*DM/4, n4w = DM*DM/4;
        tohalf_kernel<<<(n4x+255)/256, 256>>>((const float4*)x,  (uint2*)xh,  n4x);
        tohalf_kernel<<<(n4w+255)/256, 256>>>((const float4*)wq, (uint2*)wqh, n4w);
        tohalf_kernel<<<(n4w+255)/256, 256>>>((const float4*)wk, (uint2*)wkh, n4w);
        tohalf_kernel<<<(n4w+255)/256, 256>>>((const float4*)wv, (uint2*)wvh, n4w);
        tohalf_kernel<<<(n4w+255)/256, 256>>>((const float4*)wo, (uint2*)woh, n4w);
    }

    dim3 g1(8, 32, 3);
    qkv_mma_kernel<<<g1, 256, GQ_SMEM>>>(bq, bk, bv);

    dim3 g2(16, 32);
    fattn_kernel<<<g2, 256, FA_SMEM>>>(attn);

    dim3 g3(8, 32);
    outproj_mma_kernel<<<g3, 256, GQ_SMEM>>>(bo, out);

    norm_attn_kernel<<<BHT * SEQ, 256>>>(attn);
}

// round 6
// speedup vs baseline: 4.3419x; 1.2235x over previous
#include <cuda_runtime.h>
#include <cuda_bf16.h>
#include <cuda_fp16.h>
#include <math.h>
#include <stdint.h>

#define BD   2
#define SEQ  2048
#define DM   1024
#define NH   16
#define DH   64
#define MTOT (BD*SEQ)    // 4096
#define BHT  (BD*NH)     // 32

// ---------------------------------------------------------------------------
// scratch (__device__ globals; allocation-free rule)
// ---------------------------------------------------------------------------
__device__ __half g_q  [BHT*SEQ*DH];     // RoPE'd Q, fp16 [bh][s][d]
__device__ __half g_k  [BHT*SEQ*DH];     // RoPE'd K
__device__ __half g_v  [BHT*SEQ*DH];     // V
__device__ __half g_xh [MTOT*DM];        // x in fp16
__device__ __half g_wq [DM*DM], g_wk[DM*DM], g_wv[DM*DM], g_wo[DM*DM];
__device__ __half g_ohf[MTOT*DM];        // head outputs [token][dmodel] fp16

// ---------------------------------------------------------------------------
// warp-MMA helpers (sm_80+ PTX, plain sm_103 target)
// ---------------------------------------------------------------------------
__device__ __forceinline__ uint32_t smem_u32(const void* p) {
    uint32_t a;
    asm("{ .reg .u64 t; cvta.to.shared.u64 t, %1; cvt.u32.u64 %0, t; }" : "=r"(a) : "l"(p));
    return a;
}
__device__ __forceinline__ void ldsm4(uint32_t r[4], uint32_t addr) {
    asm volatile("ldmatrix.sync.aligned.m8n8.x4.shared.b16 {%0,%1,%2,%3}, [%4];"
        : "=r"(r[0]), "=r"(r[1]), "=r"(r[2]), "=r"(r[3]) : "r"(addr));
}
__device__ __forceinline__ void ldsm4t(uint32_t r[4], uint32_t addr) {
    asm volatile("ldmatrix.sync.aligned.m8n8.x4.trans.shared.b16 {%0,%1,%2,%3}, [%4];"
        : "=r"(r[0]), "=r"(r[1]), "=r"(r[2]), "=r"(r[3]) : "r"(addr));
}
__device__ __forceinline__ void mmah(float* c, const uint32_t* a, uint32_t b0, uint32_t b1) {
    asm volatile("mma.sync.aligned.m16n8k16.row.col.f32.f16.f16.f32 "
        "{%0,%1,%2,%3}, {%4,%5,%6,%7}, {%8,%9}, {%0,%1,%2,%3};"
        : "+f"(c[0]), "+f"(c[1]), "+f"(c[2]), "+f"(c[3])
        : "r"(a[0]), "r"(a[1]), "r"(a[2]), "r"(a[3]), "r"(b0), "r"(b1));
}
__device__ __forceinline__ void cp16(uint32_t dst, const void* src) {
    asm volatile("cp.async.cg.shared.global [%0], [%1], 16;" :: "r"(dst), "l"(src));
}
#define CP_COMMIT() asm volatile("cp.async.commit_group;" ::: "memory")
#define CP_WAIT0()  asm volatile("cp.async.wait_group 0;" ::: "memory")
#define SW(o) ((o) ^ (((o) >> 3) & 0x70))

__device__ __forceinline__ uint32_t h2pack(float a, float b) {
    __half2 h = __floats2half2_rn(a, b);
    return *(uint32_t*)&h;
}

// ---------------------------------------------------------------------------
// prep: fp32 -> fp16
// ---------------------------------------------------------------------------
__global__ __launch_bounds__(256) void tohalf_kernel(
    const float4* __restrict__ src, uint2* __restrict__ dst, int n4)
{
    int i = blockIdx.x * 256 + threadIdx.x;
    if (i >= n4) return;
    float4 v = src[i];
    uint2 o;
    o.x = h2pack(v.x, v.y);
    o.y = h2pack(v.z, v.w);
    dst[i] = o;
}

// ---------------------------------------------------------------------------
// GEMM core (single fp16 HMMA): C(128x128) = A(128xK) @ B(KxN), K-tiles of 64
// ---------------------------------------------------------------------------
#define GQ_A    0
#define GQ_B    16384
#define GQ_FREQ 32768
#define GQ_SMEM (GQ_FREQ + 128)

__device__ __forceinline__ void gemm_tile_load_h(
    char* smem, int tid, int m0, int n0, int k0,
    const __half* A, int lda, const __half* B, int ldb)
{
    #pragma unroll
    for (int i = 0; i < 4; i++) {
        int c = tid + i*256;
        int row = c >> 3, part = c & 7;
        uint32_t off = SW((uint32_t)(row*128 + part*16));
        *(uint4*)(smem + GQ_A + off) = *(const uint4*)(A + (size_t)(m0+row)*lda + k0 + part*8);
    }
    #pragma unroll
    for (int i = 0; i < 4; i++) {
        int c = tid + i*256;
        int krow = c >> 4, chunk = c & 15;
        int half_ = chunk >> 3, nl = (chunk & 7) * 8;
        uint32_t off = (uint32_t)(half_*8192) + SW((uint32_t)(krow*128 + nl*2));
        *(uint4*)(smem + GQ_B + off) = *(const uint4*)(B + (size_t)(k0+krow)*ldb + n0 + chunk*8);
    }
}

__device__ __forceinline__ void gemm_tile_mma_h(
    uint32_t sb, int lane, int wy, int wx, float acc[4][4][4])
{
    const int g = lane >> 3;
    const int arow = wy*64 + (lane & 7) + ((lane >> 3) & 1) * 8;
    #pragma unroll
    for (int ks = 0; ks < 4; ks++) {
        uint32_t a[4][4];
        const uint32_t abase = (uint32_t)(arow*128 + ks*32 + (lane & 16));
        #pragma unroll
        for (int mt = 0; mt < 4; mt++)
            ldsm4(a[mt], sb + GQ_A + SW(abase + mt*16*128));
        #pragma unroll
        for (int np = 0; np < 2; np++) {
            const int krow = ks*16 + (g & 1)*8 + (lane & 7);
            const int nlg = wx*32 + np*16 + (g >> 1)*8;
            const uint32_t boff = (uint32_t)((nlg >> 6)*8192) + SW((uint32_t)(krow*128 + (nlg & 63)*2));
            uint32_t b[4];
            ldsm4t(b, sb + GQ_B + boff);
            #pragma unroll
            for (int mt = 0; mt < 4; mt++) {
                mmah(acc[mt][np*2+0], a[mt], b[0], b[1]);
                mmah(acc[mt][np*2+1], a[mt], b[2], b[3]);
            }
        }
    }
}

// ---------------------------------------------------------------------------
// QKV projection; epilogue: +bias, RoPE (q,k), store fp16 [bh][s][d]
// ---------------------------------------------------------------------------
__global__ __launch_bounds__(256) void qkv_mma_kernel(
    const float* __restrict__ bq, const float* __restrict__ bk, const float* __restrict__ bv)
{
    extern __shared__ __align__(1024) char smem[];
    const uint32_t sb = smem_u32(smem);
    const int tid = threadIdx.x, wid = tid >> 5, lane = tid & 31;
    const int wy = wid >> 2, wx = wid & 3;
    const int n0 = blockIdx.x * 128;
    const int m0 = blockIdx.y * 128;
    const int z = blockIdx.z;

    const __half* B    = (z==0) ? g_wq : (z==1) ? g_wk : g_wv;
    const float* bias  = (z==0) ? bq   : (z==1) ? bk   : bv;

    float* s_freq = (float*)(smem + GQ_FREQ);
    if (tid < 32)
        s_freq[tid] = (float)(1.0 / pow(10000.0, (double)(2*tid) / 64.0));

    float acc[4][4][4];
    #pragma unroll
    for (int a = 0; a < 4; a++)
        #pragma unroll
        for (int b = 0; b < 4; b++)
            #pragma unroll
            for (int c = 0; c < 4; c++) acc[a][b][c] = 0.f;

    for (int k0 = 0; k0 < DM; k0 += 64) {
        gemm_tile_load_h(smem, tid, m0, n0, k0, g_xh, DM, B, DM);
        __syncthreads();
        gemm_tile_mma_h(sb, lane, wy, wx, acc);
        __syncthreads();
    }

    __half* dst = (z==0) ? g_q : (z==1) ? g_k : g_v;
    const int gr = lane >> 2, qc = (lane & 3) * 2;
    #pragma unroll
    for (int mt = 0; mt < 4; mt++) {
        #pragma unroll
        for (int h = 0; h < 2; h++) {
            int r = m0 + wy*64 + mt*16 + h*8 + gr;
            int bb = r >> 11;
            int s  = r & 2047;
            #pragma unroll
            for (int nt = 0; nt < 4; nt++) {
                int c = n0 + wx*32 + nt*8 + qc;   // even col
                float v0 = acc[mt][nt][h*2+0] + bias[c];
                float v1 = acc[mt][nt][h*2+1] + bias[c+1];
                float ox = v0, oy = v1;
                if (z < 2) {
                    float fr = s_freq[(c & 63) >> 1];
                    float sn, cs;
                    sincosf((float)s * fr, &sn, &cs);
                    ox = v0*cs - v1*sn;
                    oy = v0*sn + v1*cs;
                }
                int bh = bb*NH + (c >> 6);
                size_t idx = ((size_t)bh*SEQ + s)*DH + (c & 63);
                *(uint32_t*)(dst + idx) = h2pack(ox, oy);
            }
        }
    }
}

// ---------------------------------------------------------------------------
// Fused attention, TWO-PASS:
//   Pass A: loop K/V chunks: S=QK^T, exp, rowsum, PV accumulate. NO gmem write.
//   Pass B: recompute S per chunk, write exp(S/8)*inv (normalized attn) once.
// 8 warps, warp = 16 m-rows; block = 128 rows of one bh.
// ---------------------------------------------------------------------------
#define FA_SQ   0
#define FA_K0   16384
#define FA_K1   24576
#define FA_V0   32768
#define FA_V1   40960
#define FA_SMEM 49152

__device__ __forceinline__ void fa_prefetch_kv(uint32_t sb, int buf, int bh, int k0, int tid)
{
    const __half* kp = g_k + ((size_t)bh*SEQ + k0)*DH;
    const __half* vp = g_v + ((size_t)bh*SEQ + k0)*DH;
    const uint32_t kb = sb + (buf ? FA_K1 : FA_K0);
    const uint32_t vb = sb + (buf ? FA_V1 : FA_V0);
    #pragma unroll
    for (int i = 0; i < 2; i++) {
        int c = tid + i*256;
        int row = c >> 3, part = c & 7;
        uint32_t off = SW((uint32_t)(row*128 + part*16));
        cp16(kb + off, kp + (size_t)row*DH + part*8);
        cp16(vb + off, vp + (size_t)row*DH + part*8);
    }
}

__device__ __forceinline__ void fa_prefetch_k(uint32_t sb, int buf, int bh, int k0, int tid)
{
    const __half* kp = g_k + ((size_t)bh*SEQ + k0)*DH;
    const uint32_t kb = sb + (buf ? FA_K1 : FA_K0);
    #pragma unroll
    for (int i = 0; i < 2; i++) {
        int c = tid + i*256;
        int row = c >> 3, part = c & 7;
        uint32_t off = SW((uint32_t)(row*128 + part*16));
        cp16(kb + off, kp + (size_t)row*DH + part*8);
    }
}

__global__ __launch_bounds__(256) void fattn_kernel(float* __restrict__ attn)
{
    extern __shared__ __align__(1024) char smem[];
    const uint32_t sb = smem_u32(smem);
    const int tid = threadIdx.x, wid = tid >> 5, lane = tid & 31;
    const int m0 = blockIdx.x * 128;
    const int bh = blockIdx.y;
    const int g = lane >> 3, gr = lane >> 2, qc = (lane & 3) * 2;

    // load Q tile (128 x 64 fp16, swizzled)
    {
        const uint4* qsrc = (const uint4*)(g_q + ((size_t)bh*SEQ + m0)*DH);
        #pragma unroll
        for (int i = 0; i < 4; i++) {
            int c = tid + i*256;
            int row = c >> 3, part = c & 7;
            *(uint4*)(smem + FA_SQ + SW((uint32_t)(row*128 + part*16))) = qsrc[row*8 + part];
        }
    }
    fa_prefetch_kv(sb, 0, bh, 0, tid);
    CP_COMMIT();
    __syncthreads();

    // per-warp persistent Q fragments (16 m-rows x 64 k)
    uint32_t qf[4][4];
    {
        const int arow = wid*16 + (lane & 7) + ((lane >> 3) & 1)*8;
        #pragma unroll
        for (int ks = 0; ks < 4; ks++)
            ldsm4(qf[ks], sb + FA_SQ + SW((uint32_t)(arow*128 + ks*32 + (lane & 16))));
    }

    float o[8][4];
    #pragma unroll
    for (int t = 0; t < 8; t++)
        #pragma unroll
        for (int j = 0; j < 4; j++) o[t][j] = 0.f;
    float rs0 = 0.f, rs1 = 0.f;

    // ------------------- PASS A: rowsum + PV (no gmem writes) ---------------
    for (int kt = 0; kt < 32; kt++) {
        CP_WAIT0();
        __syncthreads();
        if (kt < 31) { fa_prefetch_kv(sb, (kt+1) & 1, bh, (kt+1)*64, tid); CP_COMMIT(); }

        const uint32_t kb = sb + ((kt & 1) ? FA_K1 : FA_K0);
        const uint32_t vb = sb + ((kt & 1) ? FA_V1 : FA_V0);

        float S[8][4];
        #pragma unroll
        for (int t = 0; t < 8; t++)
            #pragma unroll
            for (int j = 0; j < 4; j++) S[t][j] = 0.f;

        #pragma unroll
        for (int np = 0; np < 4; np++) {
            const int nrow = np*16 + (g >> 1)*8 + (lane & 7);
            #pragma unroll
            for (int ks = 0; ks < 4; ks++) {
                uint32_t bK[4];
                ldsm4(bK, kb + SW((uint32_t)(nrow*128 + ks*32 + (g & 1)*16)));
                mmah(S[np*2+0], qf[ks], bK[0], bK[1]);
                mmah(S[np*2+1], qf[ks], bK[2], bK[3]);
            }
        }

        #pragma unroll
        for (int t = 0; t < 8; t++) {
            S[t][0] = __expf(S[t][0] * 0.125f);
            S[t][1] = __expf(S[t][1] * 0.125f);
            S[t][2] = __expf(S[t][2] * 0.125f);
            S[t][3] = __expf(S[t][3] * 0.125f);
            rs0 += S[t][0] + S[t][1];
            rs1 += S[t][2] + S[t][3];
        }

        #pragma unroll
        for (int kk = 0; kk < 4; kk++) {
            uint32_t aP[4];
            aP[0] = h2pack(S[2*kk  ][0], S[2*kk  ][1]);
            aP[1] = h2pack(S[2*kk  ][2], S[2*kk  ][3]);
            aP[2] = h2pack(S[2*kk+1][0], S[2*kk+1][1]);
            aP[3] = h2pack(S[2*kk+1][2], S[2*kk+1][3]);
            const int krow = kk*16 + (g & 1)*8 + (lane & 7);
            #pragma unroll
            for (int np = 0; np < 4; np++) {
                const int ncol = np*16 + (g >> 1)*8;
                uint32_t bV[4];
                ldsm4t(bV, vb + SW((uint32_t)(krow*128 + ncol*2)));
                mmah(o[np*2+0], aP, bV[0], bV[1]);
                mmah(o[np*2+1], aP, bV[2], bV[3]);
            }
        }
    }

    // rowsum reduce within quad
    rs0 += __shfl_xor_sync(0xffffffffu, rs0, 1);
    rs0 += __shfl_xor_sync(0xffffffffu, rs0, 2);
    rs1 += __shfl_xor_sync(0xffffffffu, rs1, 1);
    rs1 += __shfl_xor_sync(0xffffffffu, rs1, 2);
    const float inv0 = 1.f / rs0;
    const float inv1 = 1.f / rs1;

    // all warps done reading pass-A buffers before pass B overwrites K0
    __syncthreads();
    fa_prefetch_k(sb, 0, bh, 0, tid);
    CP_COMMIT();

    // overlap: write normalized head outputs (fp16) while cp.async flies
    const int row0 = m0 + wid*16 + gr;
    {
        const int bb = bh >> 4, hh = bh & 15;
        __half* o0 = g_ohf + ((size_t)bb*SEQ + row0)*DM + hh*64;
        __half* o1 = o0 + 8*DM;
        #pragma unroll
        for (int t = 0; t < 8; t++) {
            *(uint32_t*)(o0 + t*8 + qc) = h2pack(o[t][0]*inv0, o[t][1]*inv0);
            *(uint32_t*)(o1 + t*8 + qc) = h2pack(o[t][2]*inv1, o[t][3]*inv1);
        }
    }

    // ------------------- PASS B: recompute S, write normalized attn ---------
    float* arow0 = attn + ((size_t)bh*SEQ + row0)*SEQ;
    float* arow1 = arow0 + 8*SEQ;

    for (int kt = 0; kt < 32; kt++) {
        CP_WAIT0();
        __syncthreads();
        if (kt < 31) { fa_prefetch_k(sb, (kt+1) & 1, bh, (kt+1)*64, tid); CP_COMMIT(); }

        const uint32_t kb = sb + ((kt & 1) ? FA_K1 : FA_K0);

        float S[8][4];
        #pragma unroll
        for (int t = 0; t < 8; t++)
            #pragma unroll
            for (int j = 0; j < 4; j++) S[t][j] = 0.f;

        #pragma unroll
        for (int np = 0; np < 4; np++) {
            const int nrow = np*16 + (g >> 1)*8 + (lane & 7);
            #pragma unroll
            for (int ks = 0; ks < 4; ks++) {
                uint32_t bK[4];
                ldsm4(bK, kb + SW((uint32_t)(nrow*128 + ks*32 + (g & 1)*16)));
                mmah(S[np*2+0], qf[ks], bK[0], bK[1]);
                mmah(S[np*2+1], qf[ks], bK[2], bK[3]);
            }
        }

        #pragma unroll
        for (int t = 0; t < 8; t++) {
            float e0 = __expf(S[t][0] * 0.125f) * inv0;
            float e1 = __expf(S[t][1] * 0.125f) * inv0;
            float e2 = __expf(S[t][2] * 0.125f) * inv1;
            float e3 = __expf(S[t][3] * 0.125f) * inv1;
            int col = kt*64 + t*8 + qc;
            *(float2*)(arow0 + col) = make_float2(e0, e1);
            *(float2*)(arow1 + col) = make_float2(e2, e3);
        }
    }
}

// ---------------------------------------------------------------------------
// Output projection: out = oh @ Wo + bo
// ---------------------------------------------------------------------------
__global__ __launch_bounds__(256) void outproj_mma_kernel(
    const float* __restrict__ bo, float* __restrict__ out)
{
    extern __shared__ __align__(1024) char smem[];
    const uint32_t sb = smem_u32(smem);
    const int tid = threadIdx.x, wid = tid >> 5, lane = tid & 31;
    const int wy = wid >> 2, wx = wid & 3;
    const int n0 = blockIdx.x * 128;
    const int m0 = blockIdx.y * 128;

    float acc[4][4][4];
    #pragma unroll
    for (int a = 0; a < 4; a++)
        #pragma unroll
        for (int b = 0; b < 4; b++)
            #pragma unroll
            for (int c = 0; c < 4; c++) acc[a][b][c] = 0.f;

    for (int k0 = 0; k0 < DM; k0 += 64) {
        gemm_tile_load_h(smem, tid, m0, n0, k0, g_ohf, DM, g_wo, DM);
        __syncthreads();
        gemm_tile_mma_h(sb, lane, wy, wx, acc);
        __syncthreads();
    }

    const int gr = lane >> 2, qc = (lane & 3) * 2;
    #pragma unroll
    for (int mt = 0; mt < 4; mt++) {
        #pragma unroll
        for (int h = 0; h < 2; h++) {
            int r = m0 + wy*64 + mt*16 + h*8 + gr;
            #pragma unroll
            for (int nt = 0; nt < 4; nt++) {
                int c = n0 + wx*32 + nt*8 + qc;
                float2 oo;
                oo.x = acc[mt][nt][h*2+0] + bo[c];
                oo.y = acc[mt][nt][h*2+1] + bo[c+1];
                *(float2*)(out + (size_t)r*DM + c) = oo;
            }
        }
    }
}

// ---------------------------------------------------------------------------
extern "C" void kernel_launch(void* const* d_in, const int* in_sizes, int n_in,
                              void* d_out, int out_size)
{
    const float* x  = (const float*)d_in[0];
    const float* wq = (const float*)d_in[1];
    const float* bq = (const float*)d_in[2];
    const float* wk = (const float*)d_in[3];
    const float* bk = (const float*)d_in[4];
    const float* wv = (const float*)d_in[5];
    const float* bv = (const float*)d_in[6];
    const float* wo = (const float*)d_in[7];
    const float* bo = (const float*)d_in[8];

    float* out  = (float*)d_out;
    float* attn = out + (size_t)MTOT * DM;   // tuple order: (out, attn)

    static bool attr_set = false;
    if (!attr_set) {
        cudaFuncSetAttribute(qkv_mma_kernel,     cudaFuncAttributeMaxDynamicSharedMemorySize, GQ_SMEM);
        cudaFuncSetAttribute(outproj_mma_kernel, cudaFuncAttributeMaxDynamicSharedMemorySize, GQ_SMEM);
        cudaFuncSetAttribute(fattn_kernel,       cudaFuncAttributeMaxDynamicSharedMemorySize, FA_SMEM);
        attr_set = true;
    }

    {
        __half *xh, *wqh, *wkh, *wvh, *woh;
        cudaGetSymbolAddress((void**)&xh,  g_xh);
        cudaGetSymbolAddress((void**)&wqh, g_wq);
        cudaGetSymbolAddress((void**)&wkh, g_wk);
        cudaGetSymbolAddress((void**)&wvh, g_wv);
        cudaGetSymbolAddress((void**)&woh, g_wo);

        int n4x = MTOT*DM/4, n4w = DM*DM/4;
        tohalf_kernel<<<(n4x+255)/256, 256>>>((const float4*)x,  (uint2*)xh,  n4x);
        tohalf_kernel<<<(n4w+255)/256, 256>>>((const float4*)wq, (uint2*)wqh, n4w);
        tohalf_kernel<<<(n4w+255)/256, 256>>>((const float4*)wk, (uint2*)wkh, n4w);
        tohalf_kernel<<<(n4w+255)/256, 256>>>((const float4*)wv, (uint2*)wvh, n4w);
        tohalf_kernel<<<(n4w+255)/256, 256>>>((const float4*)wo, (uint2*)woh, n4w);
    }

    dim3 g1(8, 32, 3);
    qkv_mma_kernel<<<g1, 256, GQ_SMEM>>>(bq, bk, bv);

    dim3 g2(16, 32);
    fattn_kernel<<<g2, 256, FA_SMEM>>>(attn);

    dim3 g3(8, 32);
    outproj_mma_kernel<<<g3, 256, GQ_SMEM>>>(bo, out);
}

// round 7
// speedup vs baseline: 5.4796x; 1.2621x over previous
#include <cuda_runtime.h>
#include <cuda_bf16.h>
#include <cuda_fp16.h>
#include <math.h>
#include <stdint.h>

#define BD   2
#define SEQ  2048
#define DM   1024
#define NH   16
#define DH   64
#define MTOT (BD*SEQ)    // 4096
#define BHT  (BD*NH)     // 32

// Q pre-scale: 0.125 * log2(e) so scores arrive in log2 units
#define QSCALE 0.18033688011112042f
#define ONESH2 0x3C003C00u

// ---------------------------------------------------------------------------
// scratch (__device__ globals; allocation-free rule)
// ---------------------------------------------------------------------------
__device__ __half g_q  [BHT*SEQ*DH];     // RoPE'd Q (pre-scaled), fp16 [bh][s][d]
__device__ __half g_k  [BHT*SEQ*DH];     // RoPE'd K
__device__ __half g_v  [BHT*SEQ*DH];     // V
__device__ __half g_xh [MTOT*DM];        // x in fp16
__device__ __half g_wq [DM*DM], g_wk[DM*DM], g_wv[DM*DM], g_wo[DM*DM];
__device__ __half g_ohf[MTOT*DM];        // head outputs [token][dmodel] fp16

// ---------------------------------------------------------------------------
// helpers
// ---------------------------------------------------------------------------
__device__ __forceinline__ uint32_t smem_u32(const void* p) {
    uint32_t a;
    asm("{ .reg .u64 t; cvta.to.shared.u64 t, %1; cvt.u32.u64 %0, t; }" : "=r"(a) : "l"(p));
    return a;
}
__device__ __forceinline__ void ldsm4(uint32_t r[4], uint32_t addr) {
    asm volatile("ldmatrix.sync.aligned.m8n8.x4.shared.b16 {%0,%1,%2,%3}, [%4];"
        : "=r"(r[0]), "=r"(r[1]), "=r"(r[2]), "=r"(r[3]) : "r"(addr));
}
__device__ __forceinline__ void ldsm4t(uint32_t r[4], uint32_t addr) {
    asm volatile("ldmatrix.sync.aligned.m8n8.x4.trans.shared.b16 {%0,%1,%2,%3}, [%4];"
        : "=r"(r[0]), "=r"(r[1]), "=r"(r[2]), "=r"(r[3]) : "r"(addr));
}
__device__ __forceinline__ void mmah(float* c, const uint32_t* a, uint32_t b0, uint32_t b1) {
    asm volatile("mma.sync.aligned.m16n8k16.row.col.f32.f16.f16.f32 "
        "{%0,%1,%2,%3}, {%4,%5,%6,%7}, {%8,%9}, {%0,%1,%2,%3};"
        : "+f"(c[0]), "+f"(c[1]), "+f"(c[2]), "+f"(c[3])
        : "r"(a[0]), "r"(a[1]), "r"(a[2]), "r"(a[3]), "r"(b0), "r"(b1));
}
__device__ __forceinline__ void cp16(uint32_t dst, const void* src) {
    asm volatile("cp.async.cg.shared.global [%0], [%1], 16;" :: "r"(dst), "l"(src));
}
#define CP_COMMIT() asm volatile("cp.async.commit_group;" ::: "memory")
#define CP_WAIT0()  asm volatile("cp.async.wait_group 0;" ::: "memory")
#define SW(o) ((o) ^ (((o) >> 3) & 0x70))

__device__ __forceinline__ uint32_t h2pack(float a, float b) {
    __half2 h = __floats2half2_rn(a, b);
    return *(uint32_t*)&h;
}
__device__ __forceinline__ uint32_t cvt_f16x2(float hi, float lo) {
    uint32_t d; asm("cvt.rn.f16x2.f32 %0, %1, %2;" : "=r"(d) : "f"(hi), "f"(lo)); return d;
}
__device__ __forceinline__ uint32_t ex2_f16x2(uint32_t a) {
    uint32_t d; asm("ex2.approx.f16x2 %0, %1;" : "=r"(d) : "r"(a)); return d;
}
__device__ __forceinline__ float ex2f(float a) {
    float d; asm("ex2.approx.f32 %0, %1;" : "=f"(d) : "f"(a)); return d;
}

// ---------------------------------------------------------------------------
// prep: fp32 -> fp16 (x separately; 4 weights in one launch)
// ---------------------------------------------------------------------------
__global__ __launch_bounds__(256) void tohalf_kernel(
    const float4* __restrict__ src, uint2* __restrict__ dst, int n4)
{
    int i = blockIdx.x * 256 + threadIdx.x;
    if (i >= n4) return;
    float4 v = src[i];
    uint2 o;
    o.x = h2pack(v.x, v.y);
    o.y = h2pack(v.z, v.w);
    dst[i] = o;
}

__global__ __launch_bounds__(256) void tohalf4_kernel(
    const float4* __restrict__ s0, const float4* __restrict__ s1,
    const float4* __restrict__ s2, const float4* __restrict__ s3,
    uint2* __restrict__ d0, uint2* __restrict__ d1,
    uint2* __restrict__ d2, uint2* __restrict__ d3, int n4)
{
    int y = blockIdx.y;
    const float4* s = (y==0) ? s0 : (y==1) ? s1 : (y==2) ? s2 : s3;
    uint2* d       = (y==0) ? d0 : (y==1) ? d1 : (y==2) ? d2 : d3;
    int i = blockIdx.x * 256 + threadIdx.x;
    if (i >= n4) return;
    float4 v = s[i];
    uint2 o;
    o.x = h2pack(v.x, v.y);
    o.y = h2pack(v.z, v.w);
    d[i] = o;
}

// ---------------------------------------------------------------------------
// GEMM core (fp16 HMMA, cp.async 2-stage): C(128x128) = A(128xK) @ B(KxN)
// stage = A tile (16KB) + B tile (16KB, two 64-col halves); 2 stages.
// 8 warps, warp tile 64m x 32n.
// ---------------------------------------------------------------------------
#define GQ_STG  32768
#define GQ_FREQ 65536
#define GQ_SMEM (GQ_FREQ + 128)

__device__ __forceinline__ void gemm_prefetch(
    uint32_t sb, int buf, int tid, int m0, int n0, int k0,
    const __half* A, int lda, const __half* B, int ldb)
{
    const uint32_t ab = sb + buf*GQ_STG;
    const uint32_t bb = ab + 16384;
    #pragma unroll
    for (int i = 0; i < 4; i++) {
        int c = tid + i*256;
        int row = c >> 3, part = c & 7;
        cp16(ab + SW((uint32_t)(row*128 + part*16)), A + (size_t)(m0+row)*lda + k0 + part*8);
    }
    #pragma unroll
    for (int i = 0; i < 4; i++) {
        int c = tid + i*256;
        int krow = c >> 4, chunk = c & 15;
        int half_ = chunk >> 3, nl = (chunk & 7) * 8;
        cp16(bb + (uint32_t)(half_*8192) + SW((uint32_t)(krow*128 + nl*2)),
             B + (size_t)(k0+krow)*ldb + n0 + chunk*8);
    }
}

__device__ __forceinline__ void gemm_tile_mma_h(
    uint32_t base, int lane, int wy, int wx, float acc[4][4][4])
{
    const uint32_t ba = base, bbb = base + 16384;
    const int g = lane >> 3;
    const int arow = wy*64 + (lane & 7) + ((lane >> 3) & 1) * 8;
    #pragma unroll
    for (int ks = 0; ks < 4; ks++) {
        uint32_t a[4][4];
        const uint32_t abase = (uint32_t)(arow*128 + ks*32 + (lane & 16));
        #pragma unroll
        for (int mt = 0; mt < 4; mt++)
            ldsm4(a[mt], ba + SW(abase + mt*16*128));
        #pragma unroll
        for (int np = 0; np < 2; np++) {
            const int krow = ks*16 + (g & 1)*8 + (lane & 7);
            const int nlg = wx*32 + np*16 + (g >> 1)*8;
            const uint32_t boff = (uint32_t)((nlg >> 6)*8192) + SW((uint32_t)(krow*128 + (nlg & 63)*2));
            uint32_t b[4];
            ldsm4t(b, bbb + boff);
            #pragma unroll
            for (int mt = 0; mt < 4; mt++) {
                mmah(acc[mt][np*2+0], a[mt], b[0], b[1]);
                mmah(acc[mt][np*2+1], a[mt], b[2], b[3]);
            }
        }
    }
}

// ---------------------------------------------------------------------------
// QKV projection; epilogue: +bias, RoPE (q,k), Q pre-scaled, store fp16
// ---------------------------------------------------------------------------
__global__ __launch_bounds__(256) void qkv_mma_kernel(
    const float* __restrict__ bq, const float* __restrict__ bk, const float* __restrict__ bv)
{
    extern __shared__ __align__(1024) char smem[];
    const uint32_t sb = smem_u32(smem);
    const int tid = threadIdx.x, wid = tid >> 5, lane = tid & 31;
    const int wy = wid >> 2, wx = wid & 3;
    const int n0 = blockIdx.x * 128;
    const int m0 = blockIdx.y * 128;
    const int z = blockIdx.z;

    const __half* B    = (z==0) ? g_wq : (z==1) ? g_wk : g_wv;
    const float* bias  = (z==0) ? bq   : (z==1) ? bk   : bv;

    float* s_freq = (float*)(smem + GQ_FREQ);
    if (tid < 32)
        s_freq[tid] = (float)(1.0 / pow(10000.0, (double)(2*tid) / 64.0));

    float acc[4][4][4];
    #pragma unroll
    for (int a = 0; a < 4; a++)
        #pragma unroll
        for (int b = 0; b < 4; b++)
            #pragma unroll
            for (int c = 0; c < 4; c++) acc[a][b][c] = 0.f;

    gemm_prefetch(sb, 0, tid, m0, n0, 0, g_xh, DM, B, DM);
    CP_COMMIT();
    for (int kt = 0; kt < 16; kt++) {
        CP_WAIT0();
        __syncthreads();
        if (kt < 15) {
            gemm_prefetch(sb, (kt+1) & 1, tid, m0, n0, (kt+1)*64, g_xh, DM, B, DM);
            CP_COMMIT();
        }
        gemm_tile_mma_h(sb + (kt & 1)*GQ_STG, lane, wy, wx, acc);
    }

    __half* dst = (z==0) ? g_q : (z==1) ? g_k : g_v;
    const int gr = lane >> 2, qc = (lane & 3) * 2;
    #pragma unroll
    for (int mt = 0; mt < 4; mt++) {
        #pragma unroll
        for (int h = 0; h < 2; h++) {
            int r = m0 + wy*64 + mt*16 + h*8 + gr;
            int bb = r >> 11;
            int s  = r & 2047;
            #pragma unroll
            for (int nt = 0; nt < 4; nt++) {
                int c = n0 + wx*32 + nt*8 + qc;   // even col
                float v0 = acc[mt][nt][h*2+0] + bias[c];
                float v1 = acc[mt][nt][h*2+1] + bias[c+1];
                float ox = v0, oy = v1;
                if (z < 2) {
                    float fr = s_freq[(c & 63) >> 1];
                    float sn, cs;
                    sincosf((float)s * fr, &sn, &cs);
                    ox = v0*cs - v1*sn;
                    oy = v0*sn + v1*cs;
                    if (z == 0) { ox *= QSCALE; oy *= QSCALE; }
                }
                int bh = bb*NH + (c >> 6);
                size_t idx = ((size_t)bh*SEQ + s)*DH + (c & 63);
                *(uint32_t*)(dst + idx) = h2pack(ox, oy);
            }
        }
    }
}

// ---------------------------------------------------------------------------
// Fused attention, TWO-PASS (S in log2 units — Q pre-scaled):
//   Pass A: S=QK^T, P=ex2.f16x2(S), rowsum via ones-MMA, PV accumulate.
//   Pass B: recompute S, write ex2f(S)*inv (normalized attn) once, streaming.
// ---------------------------------------------------------------------------
#define FA_SQ   0
#define FA_K0   16384
#define FA_K1   24576
#define FA_V0   32768
#define FA_V1   40960
#define FA_SMEM 49152

__device__ __forceinline__ void fa_prefetch_kv(uint32_t sb, int buf, int bh, int k0, int tid)
{
    const __half* kp = g_k + ((size_t)bh*SEQ + k0)*DH;
    const __half* vp = g_v + ((size_t)bh*SEQ + k0)*DH;
    const uint32_t kb = sb + (buf ? FA_K1 : FA_K0);
    const uint32_t vb = sb + (buf ? FA_V1 : FA_V0);
    #pragma unroll
    for (int i = 0; i < 2; i++) {
        int c = tid + i*256;
        int row = c >> 3, part = c & 7;
        uint32_t off = SW((uint32_t)(row*128 + part*16));
        cp16(kb + off, kp + (size_t)row*DH + part*8);
        cp16(vb + off, vp + (size_t)row*DH + part*8);
    }
}

__device__ __forceinline__ void fa_prefetch_k(uint32_t sb, int buf, int bh, int k0, int tid)
{
    const __half* kp = g_k + ((size_t)bh*SEQ + k0)*DH;
    const uint32_t kb = sb + (buf ? FA_K1 : FA_K0);
    #pragma unroll
    for (int i = 0; i < 2; i++) {
        int c = tid + i*256;
        int row = c >> 3, part = c & 7;
        cp16(kb + SW((uint32_t)(row*128 + part*16)), kp + (size_t)row*DH + part*8);
    }
}

__global__ __launch_bounds__(256) void fattn_kernel(float* __restrict__ attn)
{
    extern __shared__ __align__(1024) char smem[];
    const uint32_t sb = smem_u32(smem);
    const int tid = threadIdx.x, wid = tid >> 5, lane = tid & 31;
    const int m0 = blockIdx.x * 128;
    const int bh = blockIdx.y;
    const int g = lane >> 3, gr = lane >> 2, qc = (lane & 3) * 2;

    // load Q tile (128 x 64 fp16, swizzled)
    {
        const uint4* qsrc = (const uint4*)(g_q + ((size_t)bh*SEQ + m0)*DH);
        #pragma unroll
        for (int i = 0; i < 4; i++) {
            int c = tid + i*256;
            int row = c >> 3, part = c & 7;
            *(uint4*)(smem + FA_SQ + SW((uint32_t)(row*128 + part*16))) = qsrc[row*8 + part];
        }
    }
    fa_prefetch_kv(sb, 0, bh, 0, tid);
    CP_COMMIT();
    __syncthreads();

    // per-warp persistent Q fragments (16 m-rows x 64 k)
    uint32_t qf[4][4];
    {
        const int arow = wid*16 + (lane & 7) + ((lane >> 3) & 1)*8;
        #pragma unroll
        for (int ks = 0; ks < 4; ks++)
            ldsm4(qf[ks], sb + FA_SQ + SW((uint32_t)(arow*128 + ks*32 + (lane & 16))));
    }

    float o[8][4];
    #pragma unroll
    for (int t = 0; t < 8; t++)
        #pragma unroll
        for (int j = 0; j < 4; j++) o[t][j] = 0.f;
    float ors[4] = {0.f, 0.f, 0.f, 0.f};   // rowsum via ones-MMA

    // ------------------- PASS A: rowsum + PV (no gmem writes) ---------------
    for (int kt = 0; kt < 32; kt++) {
        CP_WAIT0();
        __syncthreads();
        if (kt < 31) { fa_prefetch_kv(sb, (kt+1) & 1, bh, (kt+1)*64, tid); CP_COMMIT(); }

        const uint32_t kb = sb + ((kt & 1) ? FA_K1 : FA_K0);
        const uint32_t vb = sb + ((kt & 1) ? FA_V1 : FA_V0);

        float S[8][4];
        #pragma unroll
        for (int t = 0; t < 8; t++)
            #pragma unroll
            for (int j = 0; j < 4; j++) S[t][j] = 0.f;

        #pragma unroll
        for (int np = 0; np < 4; np++) {
            const int nrow = np*16 + (g >> 1)*8 + (lane & 7);
            #pragma unroll
            for (int ks = 0; ks < 4; ks++) {
                uint32_t bK[4];
                ldsm4(bK, kb + SW((uint32_t)(nrow*128 + ks*32 + (g & 1)*16)));
                mmah(S[np*2+0], qf[ks], bK[0], bK[1]);
                mmah(S[np*2+1], qf[ks], bK[2], bK[3]);
            }
        }

        // P = 2^S in packed fp16 (S already in log2 units)
        uint32_t P01[8], P23[8];
        #pragma unroll
        for (int t = 0; t < 8; t++) {
            P01[t] = ex2_f16x2(cvt_f16x2(S[t][1], S[t][0]));
            P23[t] = ex2_f16x2(cvt_f16x2(S[t][3], S[t][2]));
        }

        #pragma unroll
        for (int kk = 0; kk < 4; kk++) {
            uint32_t aP[4];
            aP[0] = P01[2*kk];   aP[1] = P23[2*kk];
            aP[2] = P01[2*kk+1]; aP[3] = P23[2*kk+1];
            mmah(ors, aP, ONESH2, ONESH2);           // rowsum
            const int krow = kk*16 + (g & 1)*8 + (lane & 7);
            #pragma unroll
            for (int np = 0; np < 4; np++) {
                const int ncol = np*16 + (g >> 1)*8;
                uint32_t bV[4];
                ldsm4t(bV, vb + SW((uint32_t)(krow*128 + ncol*2)));
                mmah(o[np*2+0], aP, bV[0], bV[1]);
                mmah(o[np*2+1], aP, bV[2], bV[3]);
            }
        }
    }

    const float inv0 = 1.f / ors[0];
    const float inv1 = 1.f / ors[2];

    // all warps done reading pass-A buffers before pass B overwrites K0
    __syncthreads();
    fa_prefetch_k(sb, 0, bh, 0, tid);
    CP_COMMIT();

    // overlap: write normalized head outputs (fp16) while cp.async flies
    const int row0 = m0 + wid*16 + gr;
    {
        const int bb = bh >> 4, hh = bh & 15;
        __half* o0 = g_ohf + ((size_t)bb*SEQ + row0)*DM + hh*64;
        __half* o1 = o0 + 8*DM;
        #pragma unroll
        for (int t = 0; t < 8; t++) {
            *(uint32_t*)(o0 + t*8 + qc) = h2pack(o[t][0]*inv0, o[t][1]*inv0);
            *(uint32_t*)(o1 + t*8 + qc) = h2pack(o[t][2]*inv1, o[t][3]*inv1);
        }
    }

    // ------------------- PASS B: recompute S, write normalized attn ---------
    float* arow0 = attn + ((size_t)bh*SEQ + row0)*SEQ;
    float* arow1 = arow0 + 8*SEQ;

    for (int kt = 0; kt < 32; kt++) {
        CP_WAIT0();
        __syncthreads();
        if (kt < 31) { fa_prefetch_k(sb, (kt+1) & 1, bh, (kt+1)*64, tid); CP_COMMIT(); }

        const uint32_t kb = sb + ((kt & 1) ? FA_K1 : FA_K0);

        float S[8][4];
        #pragma unroll
        for (int t = 0; t < 8; t++)
            #pragma unroll
            for (int j = 0; j < 4; j++) S[t][j] = 0.f;

        #pragma unroll
        for (int np = 0; np < 4; np++) {
            const int nrow = np*16 + (g >> 1)*8 + (lane & 7);
            #pragma unroll
            for (int ks = 0; ks < 4; ks++) {
                uint32_t bK[4];
                ldsm4(bK, kb + SW((uint32_t)(nrow*128 + ks*32 + (g & 1)*16)));
                mmah(S[np*2+0], qf[ks], bK[0], bK[1]);
                mmah(S[np*2+1], qf[ks], bK[2], bK[3]);
            }
        }

        #pragma unroll
        for (int t = 0; t < 8; t++) {
            float e0 = ex2f(S[t][0]) * inv0;
            float e1 = ex2f(S[t][1]) * inv0;
            float e2 = ex2f(S[t][2]) * inv1;
            float e3 = ex2f(S[t][3]) * inv1;
            int col = kt*64 + t*8 + qc;
            __stcs((float2*)(arow0 + col), make_float2(e0, e1));
            __stcs((float2*)(arow1 + col), make_float2(e2, e3));
        }
    }
}

// ---------------------------------------------------------------------------
// Output projection: out = oh @ Wo + bo
// ---------------------------------------------------------------------------
__global__ __launch_bounds__(256) void outproj_mma_kernel(
    const float* __restrict__ bo, float* __restrict__ out)
{
    extern __shared__ __align__(1024) char smem[];
    const uint32_t sb = smem_u32(smem);
    const int tid = threadIdx.x, wid = tid >> 5, lane = tid & 31;
    const int wy = wid >> 2, wx = wid & 3;
    const int n0 = blockIdx.x * 128;
    const int m0 = blockIdx.y * 128;

    float acc[4][4][4];
    #pragma unroll
    for (int a = 0; a < 4; a++)
        #pragma unroll
        for (int b = 0; b < 4; b++)
            #pragma unroll
            for (int c = 0; c < 4; c++) acc[a][b][c] = 0.f;

    gemm_prefetch(sb, 0, tid, m0, n0, 0, g_ohf, DM, g_wo, DM);
    CP_COMMIT();
    for (int kt = 0; kt < 16; kt++) {
        CP_WAIT0();
        __syncthreads();
        if (kt < 15) {
            gemm_prefetch(sb, (kt+1) & 1, tid, m0, n0, (kt+1)*64, g_ohf, DM, g_wo, DM);
            CP_COMMIT();
        }
        gemm_tile_mma_h(sb + (kt & 1)*GQ_STG, lane, wy, wx, acc);
    }

    const int gr = lane >> 2, qc = (lane & 3) * 2;
    #pragma unroll
    for (int mt = 0; mt < 4; mt++) {
        #pragma unroll
        for (int h = 0; h < 2; h++) {
            int r = m0 + wy*64 + mt*16 + h*8 + gr;
            #pragma unroll
            for (int nt = 0; nt < 4; nt++) {
                int c = n0 + wx*32 + nt*8 + qc;
                float2 oo;
                oo.x = acc[mt][nt][h*2+0] + bo[c];
                oo.y = acc[mt][nt][h*2+1] + bo[c+1];
                *(float2*)(out + (size_t)r*DM + c) = oo;
            }
        }
    }
}

// ---------------------------------------------------------------------------
extern "C" void kernel_launch(void* const* d_in, const int* in_sizes, int n_in,
                              void* d_out, int out_size)
{
    const float* x  = (const float*)d_in[0];
    const float* wq = (const float*)d_in[1];
    const float* bq = (const float*)d_in[2];
    const float* wk = (const float*)d_in[3];
    const float* bk = (const float*)d_in[4];
    const float* wv = (const float*)d_in[5];
    const float* bv = (const float*)d_in[6];
    const float* wo = (const float*)d_in[7];
    const float* bo = (const float*)d_in[8];

    float* out  = (float*)d_out;
    float* attn = out + (size_t)MTOT * DM;   // tuple order: (out, attn)

    static bool attr_set = false;
    if (!attr_set) {
        cudaFuncSetAttribute(qkv_mma_kernel,     cudaFuncAttributeMaxDynamicSharedMemorySize, GQ_SMEM);
        cudaFuncSetAttribute(outproj_mma_kernel, cudaFuncAttributeMaxDynamicSharedMemorySize, GQ_SMEM);
        cudaFuncSetAttribute(fattn_kernel,       cudaFuncAttributeMaxDynamicSharedMemorySize, FA_SMEM);
        attr_set = true;
    }

    {
        __half *xh, *wqh, *wkh, *wvh, *woh;
        cudaGetSymbolAddress((void**)&xh,  g_xh);
        cudaGetSymbolAddress((void**)&wqh, g_wq);
        cudaGetSymbolAddress((void**)&wkh, g_wk);
        cudaGetSymbolAddress((void**)&wvh, g_wv);
        cudaGetSymbolAddress((void**)&woh, g_wo);

        int n4x = MTOT*DM/4, n4w = DM*DM/4;
        tohalf_kernel<<<(n4x+255)/256, 256>>>((const float4*)x, (uint2*)xh, n4x);
        dim3 gw((n4w+255)/256, 4);
        tohalf4_kernel<<<gw, 256>>>((const float4*)wq, (const float4*)wk,
                                    (const float4*)wv, (const float4*)wo,
                                    (uint2*)wqh, (uint2*)wkh, (uint2*)wvh, (uint2*)woh, n4w);
    }

    dim3 g1(8, 32, 3);
    qkv_mma_kernel<<<g1, 256, GQ_SMEM>>>(bq, bk, bv);

    dim3 g2(16, 32);
    fattn_kernel<<<g2, 256, FA_SMEM>>>(attn);

    dim3 g3(8, 32);
    outproj_mma_kernel<<<g3, 256, GQ_SMEM>>>(bo, out);
}